// round 14
// baseline (speedup 1.0000x reference)
#include <cuda_runtime.h>
#include <cuda_fp16.h>

#define N_NODES 100000
#define E_EDGES 1600000
#define FIN 512
#define HC1 64
#define H1 8
#define C2 16
#define NEG_SLOPE 0.2f
#define SCAN_NB ((N_NODES + 1023) / 1024)

// ---------------- scratch (static __device__, allocation-free) ----------------
__device__ __half g_h1h [(size_t)N_NODES * HC1];   // fp16 h1
__device__ float  g_al1s[(size_t)N_NODES * H1];
__device__ float  g_al1d[(size_t)N_NODES * H1];
__device__ __half g_h2h [(size_t)N_NODES * C2];    // fp16 h2 for edge2 gather
__device__ float  g_al2s[(size_t)N_NODES];
__device__ float  g_al2d[(size_t)N_NODES];
__device__ int    g_is64;
__device__ int    g_scan_ctr;

// CSR build scratch
__device__ int g_cnt      [N_NODES];
__device__ int g_incl     [N_NODES];
__device__ int g_part     [SCAN_NB + 1];
__device__ int g_row_start[N_NODES];
__device__ int g_row_end  [N_NODES];
__device__ int g_cursor   [N_NODES];
__device__ int g_csr_src  [E_EDGES];

// side stream + fork/join events (created once at program load; no device mem)
static cudaStream_t g_s2;
static cudaEvent_t  g_ev_fork, g_ev_join;
static bool g_stream_init = []() {
    cudaStreamCreateWithFlags(&g_s2, cudaStreamNonBlocking);
    cudaEventCreateWithFlags(&g_ev_fork, cudaEventDisableTiming);
    cudaEventCreateWithFlags(&g_ev_join, cudaEventDisableTiming);
    return true;
}();

__device__ __forceinline__ float leaky(float e) { return e > 0.f ? e : NEG_SLOPE * e; }

__device__ __forceinline__ float to_tf32(float f) {
    unsigned u;
    asm("cvt.rna.tf32.f32 %0, %1;" : "=r"(u) : "f"(f));
    return __uint_as_float(u);
}

// m16n8k8 tf32 mma, row.col, f32 accumulate
__device__ __forceinline__ void mma_tf32(float* d, const float* a, const float* b) {
    asm volatile(
        "mma.sync.aligned.m16n8k8.row.col.f32.tf32.tf32.f32 "
        "{%0,%1,%2,%3}, {%4,%5,%6,%7}, {%8,%9}, {%0,%1,%2,%3};\n"
        : "+f"(d[0]), "+f"(d[1]), "+f"(d[2]), "+f"(d[3])
        : "r"(__float_as_uint(a[0])), "r"(__float_as_uint(a[1])),
          "r"(__float_as_uint(a[2])), "r"(__float_as_uint(a[3])),
          "r"(__float_as_uint(b[0])), "r"(__float_as_uint(b[1])));
}

// ---------------- detect (int64 vs int32) + zero counters + reset scan ctr ----------------
__global__ void detect_zero_kernel(const int* __restrict__ ei_words) {
    int i = blockIdx.x * blockDim.x + threadIdx.x;
    if (i < N_NODES) g_cnt[i] = 0;
    if (blockIdx.x == 0) {
        __shared__ int nz;
        if (threadIdx.x == 0) nz = 0;
        __syncthreads();
        for (int j = threadIdx.x; j < 4096; j += blockDim.x)
            if (ei_words[2 * j + 1] != 0) nz = 1;
        __syncthreads();
        if (threadIdx.x == 0) {
            g_is64 = (nz == 0);
            g_scan_ctr = 0;
        }
    }
}

// ---------------- CSR build (vectorized, grid-strided) ----------------
__global__ void hist_kernel(const void* __restrict__ ei) {
    int t = blockIdx.x * blockDim.x + threadIdx.x;
    int stride = gridDim.x * blockDim.x;
    if (g_is64) {
        const longlong2* d = (const longlong2*)((const long long*)ei + E_EDGES);
        for (int j = t; j < E_EDGES / 2; j += stride) {
            longlong2 v = d[j];
            atomicAdd(&g_cnt[(int)v.x], 1);
            atomicAdd(&g_cnt[(int)v.y], 1);
        }
    } else {
        const int4* d = (const int4*)((const int*)ei + E_EDGES);
        for (int j = t; j < E_EDGES / 4; j += stride) {
            int4 v = d[j];
            atomicAdd(&g_cnt[v.x], 1);
            atomicAdd(&g_cnt[v.y], 1);
            atomicAdd(&g_cnt[v.z], 1);
            atomicAdd(&g_cnt[v.w], 1);
        }
    }
}

// block-level inclusive scan + fused cross-block exclusive scan in the last block
__global__ __launch_bounds__(1024) void scan1_kernel() {
    __shared__ int sm[1024];
    __shared__ int is_last;
    int i = blockIdx.x * 1024 + threadIdx.x;
    sm[threadIdx.x] = (i < N_NODES) ? g_cnt[i] : 0;
    __syncthreads();
#pragma unroll
    for (int off = 1; off < 1024; off <<= 1) {
        int t = (threadIdx.x >= off) ? sm[threadIdx.x - off] : 0;
        __syncthreads();
        sm[threadIdx.x] += t;
        __syncthreads();
    }
    if (i < N_NODES) g_incl[i] = sm[threadIdx.x];
    if (threadIdx.x == 1023) g_part[blockIdx.x] = sm[1023];
    __threadfence();
    if (threadIdx.x == 0)
        is_last = (atomicAdd(&g_scan_ctr, 1) == (int)gridDim.x - 1);
    __syncthreads();
    if (is_last && threadIdx.x < 32) {
        int lane = threadIdx.x;
        int run = 0;
        for (int b0 = 0; b0 < SCAN_NB; b0 += 32) {
            int idx = b0 + lane;
            int orig = (idx < SCAN_NB) ? g_part[idx] : 0;
            int v = orig;
#pragma unroll
            for (int off = 1; off < 32; off <<= 1) {
                int t = __shfl_up_sync(0xffffffffu, v, off);
                if (lane >= off) v += t;
            }
            if (idx < SCAN_NB) g_part[idx] = run + v - orig;  // exclusive
            run += __shfl_sync(0xffffffffu, v, 31);
        }
    }
}

// vectorized: 4 nodes per thread
__global__ void scan3_kernel() {
    int i4 = blockIdx.x * blockDim.x + threadIdx.x;
    if (i4 >= N_NODES / 4) return;
    int4 inc = ((const int4*)g_incl)[i4];
    int4 c   = ((const int4*)g_cnt)[i4];
    int part = g_part[(i4 * 4) >> 10];
    inc.x += part; inc.y += part; inc.z += part; inc.w += part;
    int4 st = make_int4(inc.x - c.x, inc.y - c.y, inc.z - c.z, inc.w - c.w);
    ((int4*)g_row_start)[i4] = st;
    ((int4*)g_row_end)[i4]   = inc;
    ((int4*)g_cursor)[i4]    = st;
}

__global__ void scatter_kernel(const void* __restrict__ ei) {
    int t = blockIdx.x * blockDim.x + threadIdx.x;
    int stride = gridDim.x * blockDim.x;
    if (g_is64) {
        const longlong2* s = (const longlong2*)((const long long*)ei);
        const longlong2* d = (const longlong2*)((const long long*)ei + E_EDGES);
        for (int j = t; j < E_EDGES / 2; j += stride) {
            longlong2 sv = s[j], dv = d[j];
            int p0 = atomicAdd(&g_cursor[(int)dv.x], 1);
            int p1 = atomicAdd(&g_cursor[(int)dv.y], 1);
            g_csr_src[p0] = (int)sv.x;
            g_csr_src[p1] = (int)sv.y;
        }
    } else {
        const int4* s = (const int4*)((const int*)ei);
        const int4* d = (const int4*)((const int*)ei + E_EDGES);
        for (int j = t; j < E_EDGES / 4; j += stride) {
            int4 sv = s[j], dv = d[j];
            int p0 = atomicAdd(&g_cursor[dv.x], 1);
            int p1 = atomicAdd(&g_cursor[dv.y], 1);
            int p2 = atomicAdd(&g_cursor[dv.z], 1);
            int p3 = atomicAdd(&g_cursor[dv.w], 1);
            g_csr_src[p0] = sv.x;
            g_csr_src[p1] = sv.y;
            g_csr_src[p2] = sv.z;
            g_csr_src[p3] = sv.w;
        }
    }
}

// ---------------- GEMM1 (tf32 mma, register double-buffered — proven R9): h1 = x @ W1 ----------------
__global__ __launch_bounds__(256) void gemm1_kernel(const float* __restrict__ x,
                                                    const float* __restrict__ W1,
                                                    const float* __restrict__ a1s,
                                                    const float* __restrict__ a1d) {
    __shared__ float As[128][36];
    __shared__ float Bs[32][72];
    const int tid = threadIdx.x;
    const int warp = tid >> 5, lane = tid & 31;
    const int gid = lane >> 2, tig = lane & 3;
    const int mw = (warp >> 1) * 32;
    const int nw = (warp & 1) * 32;
    const int block_row = blockIdx.x * 128;

    float acc[2][4][4];
#pragma unroll
    for (int mt = 0; mt < 2; mt++)
#pragma unroll
        for (int nt = 0; nt < 4; nt++)
#pragma unroll
            for (int j = 0; j < 4; j++) acc[mt][nt][j] = 0.f;

    float4 aR[4], bR[2];
    const int ar_r[4]  = { (tid) >> 3, (tid + 256) >> 3, (tid + 512) >> 3, (tid + 768) >> 3 };
    const int ar_c4 = tid & 7;
    const int b_kk[2]  = { tid >> 4, (tid + 256) >> 4 };
    const int b_n4 = tid & 15;

    auto gload = [&](int k0) {
#pragma unroll
        for (int p = 0; p < 4; p++) {
            int gr = block_row + ar_r[p];
            if (gr >= N_NODES) gr = N_NODES - 1;   // clamp; rows discarded in epilogue
            aR[p] = *(const float4*)(x + (size_t)gr * FIN + k0 + ar_c4 * 4);
        }
#pragma unroll
        for (int p = 0; p < 2; p++)
            bR[p] = *(const float4*)(W1 + (size_t)(k0 + b_kk[p]) * 64 + b_n4 * 4);
    };
    auto sstore = [&]() {
#pragma unroll
        for (int p = 0; p < 4; p++) {
            float4 v = aR[p];
            v.x = to_tf32(v.x); v.y = to_tf32(v.y);
            v.z = to_tf32(v.z); v.w = to_tf32(v.w);
            *(float4*)&As[ar_r[p]][ar_c4 * 4] = v;
        }
#pragma unroll
        for (int p = 0; p < 2; p++) {
            float4 v = bR[p];
            v.x = to_tf32(v.x); v.y = to_tf32(v.y);
            v.z = to_tf32(v.z); v.w = to_tf32(v.w);
            *(float4*)&Bs[b_kk[p]][b_n4 * 4] = v;
        }
    };

    gload(0);
    sstore();
    __syncthreads();

    for (int k0 = 0; k0 < FIN; k0 += 32) {
        bool more = (k0 + 32 < FIN);
        if (more) gload(k0 + 32);      // overlaps with compute below
#pragma unroll
        for (int kk = 0; kk < 32; kk += 8) {
            float a[2][4];
#pragma unroll
            for (int mt = 0; mt < 2; mt++) {
                int r = mw + mt * 16;
                a[mt][0] = As[r + gid][kk + tig];
                a[mt][1] = As[r + gid + 8][kk + tig];
                a[mt][2] = As[r + gid][kk + tig + 4];
                a[mt][3] = As[r + gid + 8][kk + tig + 4];
            }
            float b[4][2];
#pragma unroll
            for (int nt = 0; nt < 4; nt++) {
                b[nt][0] = Bs[kk + tig][nw + nt * 8 + gid];
                b[nt][1] = Bs[kk + tig + 4][nw + nt * 8 + gid];
            }
#pragma unroll
            for (int mt = 0; mt < 2; mt++)
#pragma unroll
                for (int nt = 0; nt < 4; nt++)
                    mma_tf32(acc[mt][nt], a[mt], b[nt]);
        }
        __syncthreads();
        if (more) {
            sstore();
            __syncthreads();
        }
    }

    // ---- epilogue: fp16 h1 + fused per-head attention logits ----
#pragma unroll
    for (int mt = 0; mt < 2; mt++) {
#pragma unroll
        for (int nt = 0; nt < 4; nt++) {
            int r0 = block_row + mw + mt * 16 + gid;
            int c = nw + nt * 8 + 2 * tig;
            int l = (nw + nt * 8) >> 3;          // head for this nt tile
            float as0 = __ldg(a1s + l * 8 + 2 * tig);
            float as1 = __ldg(a1s + l * 8 + 2 * tig + 1);
            float ad0 = __ldg(a1d + l * 8 + 2 * tig);
            float ad1 = __ldg(a1d + l * 8 + 2 * tig + 1);

            float vs  = acc[mt][nt][0] * as0 + acc[mt][nt][1] * as1;   // row r0
            float vd  = acc[mt][nt][0] * ad0 + acc[mt][nt][1] * ad1;
            float vs2 = acc[mt][nt][2] * as0 + acc[mt][nt][3] * as1;   // row r0+8
            float vd2 = acc[mt][nt][2] * ad0 + acc[mt][nt][3] * ad1;
#pragma unroll
            for (int off = 1; off <= 2; off <<= 1) {
                vs  += __shfl_xor_sync(0xffffffffu, vs,  off);
                vd  += __shfl_xor_sync(0xffffffffu, vd,  off);
                vs2 += __shfl_xor_sync(0xffffffffu, vs2, off);
                vd2 += __shfl_xor_sync(0xffffffffu, vd2, off);
            }

            if (r0 < N_NODES) {
                *(__half2*)(g_h1h + (size_t)r0 * 64 + c) =
                    __floats2half2_rn(acc[mt][nt][0], acc[mt][nt][1]);
                if (tig == 0) {
                    g_al1s[r0 * 8 + l] = vs;
                    g_al1d[r0 * 8 + l] = vd;
                }
            }
            if (r0 + 8 < N_NODES) {
                *(__half2*)(g_h1h + (size_t)(r0 + 8) * 64 + c) =
                    __floats2half2_rn(acc[mt][nt][2], acc[mt][nt][3]);
                if (tig == 0) {
                    g_al1s[(r0 + 8) * 8 + l] = vs2;
                    g_al1d[(r0 + 8) * 8 + l] = vd2;
                }
            }
        }
    }
}

// ---------------- edge1 fused (CSR pull + bias/ELU/GEMM2/layer-2 logits) ----------------
// One warp per dst node. After the xor reduction every lane holds the full
// normalized aggregate for its head; final1's work completes in-warp.
__global__ __launch_bounds__(256) void edge1_fused_kernel(const float* __restrict__ W2,
                                                          const float* __restrict__ b1,
                                                          const float* __restrict__ a2s,
                                                          const float* __restrict__ a2d) {
    __shared__ float W2s[64 * 17];     // stride 17 -> <=2-way bank conflict
    __shared__ float b1s[64];
    __shared__ float a2ss[16], a2ds[16];
    const int tid = threadIdx.x;
    for (int j = tid; j < 64 * 16; j += 256)
        W2s[(j >> 4) * 17 + (j & 15)] = W2[j];
    if (tid < 64) b1s[tid] = b1[tid];
    else if (tid < 80) a2ss[tid - 64] = a2s[tid - 64];
    else if (tid < 96) a2ds[tid - 80] = a2d[tid - 80];
    __syncthreads();

    int w = (blockIdx.x * blockDim.x + tid) >> 5;
    if (w >= N_NODES) return;
    const int lane = tid & 31;
    const int sub = lane >> 3, l = lane & 7;
    const int i = w;

    float ald = g_al1d[i * 8 + l];
    float acc[8];
#pragma unroll
    for (int j = 0; j < 8; j++) acc[j] = 0.f;
    float wsum = 0.f;

    if (sub == 0) {  // self-loop
        float e = g_al1s[i * 8 + l] + ald;
        float ws = expf(leaky(e));
        wsum = ws;
        uint4 hv = *(const uint4*)(g_h1h + (size_t)i * 64 + l * 8);
        float2 f0 = __half22float2(*(__half2*)&hv.x);
        float2 f1 = __half22float2(*(__half2*)&hv.y);
        float2 f2 = __half22float2(*(__half2*)&hv.z);
        float2 f3 = __half22float2(*(__half2*)&hv.w);
        acc[0] = ws * f0.x; acc[1] = ws * f0.y;
        acc[2] = ws * f1.x; acc[3] = ws * f1.y;
        acc[4] = ws * f2.x; acc[5] = ws * f2.y;
        acc[6] = ws * f3.x; acc[7] = ws * f3.y;
    }

    const int end = g_row_end[i];
    int p = g_row_start[i] + sub;
    int src = (p < end) ? g_csr_src[p] : 0;
    while (p < end) {
        int pn = p + 4;
        int srcn = (pn < end) ? g_csr_src[pn] : 0;   // prefetch next index
        float e = g_al1s[src * 8 + l] + ald;
        float wv = expf(leaky(e));
        wsum += wv;
        uint4 hv = *(const uint4*)(g_h1h + (size_t)src * 64 + l * 8);
        float2 f0 = __half22float2(*(__half2*)&hv.x);
        float2 f1 = __half22float2(*(__half2*)&hv.y);
        float2 f2 = __half22float2(*(__half2*)&hv.z);
        float2 f3 = __half22float2(*(__half2*)&hv.w);
        acc[0] += wv * f0.x; acc[1] += wv * f0.y;
        acc[2] += wv * f1.x; acc[3] += wv * f1.y;
        acc[4] += wv * f2.x; acc[5] += wv * f2.y;
        acc[6] += wv * f3.x; acc[7] += wv * f3.y;
        p = pn;
        src = srcn;
    }

#pragma unroll
    for (int off = 8; off <= 16; off <<= 1) {
        wsum += __shfl_xor_sync(0xffffffffu, wsum, off);
#pragma unroll
        for (int j = 0; j < 8; j++)
            acc[j] += __shfl_xor_sync(0xffffffffu, acc[j], off);
    }
    // every lane now holds the full reduced aggregate for head l

    // ---- fused final1: normalize + bias + ELU ----
    float inv = 1.f / wsum;
    float v[8];
#pragma unroll
    for (int j = 0; j < 8; j++) {
        float t = acc[j] * inv + b1s[l * 8 + j];
        v[j] = t > 0.f ? t : expf(t) - 1.f;
    }

    // GEMM2 partials: lane handles output quad c = sub*4..+3 over its 8 channels
    float h2p[4];
#pragma unroll
    for (int c = 0; c < 4; c++) {
        float s = 0.f;
#pragma unroll
        for (int j = 0; j < 8; j++)
            s += v[j] * W2s[(l * 8 + j) * 17 + sub * 4 + c];
        h2p[c] = s;
    }
    // reduce over heads l (lane bits 0-2)
#pragma unroll
    for (int off = 1; off <= 4; off <<= 1) {
#pragma unroll
        for (int c = 0; c < 4; c++)
            h2p[c] += __shfl_xor_sync(0xffffffffu, h2p[c], off);
    }
    // layer-2 attention logits
    float als = h2p[0] * a2ss[sub * 4 + 0] + h2p[1] * a2ss[sub * 4 + 1] +
                h2p[2] * a2ss[sub * 4 + 2] + h2p[3] * a2ss[sub * 4 + 3];
    float al2 = h2p[0] * a2ds[sub * 4 + 0] + h2p[1] * a2ds[sub * 4 + 1] +
                h2p[2] * a2ds[sub * 4 + 2] + h2p[3] * a2ds[sub * 4 + 3];
#pragma unroll
    for (int off = 8; off <= 16; off <<= 1) {
        als += __shfl_xor_sync(0xffffffffu, als, off);
        al2 += __shfl_xor_sync(0xffffffffu, al2, off);
    }

    if (l == 0) {   // lanes 0,8,16,24: write h2 quad (fp16)
        __half2 q0 = __floats2half2_rn(h2p[0], h2p[1]);
        __half2 q1 = __floats2half2_rn(h2p[2], h2p[3]);
        *(__half2*)(g_h2h + (size_t)i * 16 + sub * 4)     = q0;
        *(__half2*)(g_h2h + (size_t)i * 16 + sub * 4 + 2) = q1;
    }
    if (lane == 0) {
        g_al2s[i] = als;
        g_al2d[i] = al2;
    }
}

// ---------------- edge2 (CSR pull) + fused bias/log_softmax -> out ----------------
__global__ __launch_bounds__(256) void edge2_csr_kernel(const float* __restrict__ b2,
                                                        float* __restrict__ out) {
    int w = (blockIdx.x * blockDim.x + threadIdx.x) >> 5;
    if (w >= N_NODES) return;
    const int lane = threadIdx.x & 31;
    const int sub = lane >> 2, l = lane & 3;
    const int i = w;

    float ald = g_al2d[i];
    float acc[4];
#pragma unroll
    for (int j = 0; j < 4; j++) acc[j] = 0.f;
    float wsum = 0.f;

    if (sub == 0) {  // self-loop
        float ws = expf(leaky(g_al2s[i] + ald));
        wsum = ws;
        uint2 hv = *(const uint2*)(g_h2h + (size_t)i * 16 + l * 4);
        float2 f0 = __half22float2(*(__half2*)&hv.x);
        float2 f1 = __half22float2(*(__half2*)&hv.y);
        acc[0] = ws * f0.x; acc[1] = ws * f0.y;
        acc[2] = ws * f1.x; acc[3] = ws * f1.y;
    }

    const int end = g_row_end[i];
    int p = g_row_start[i] + sub;
    int src = (p < end) ? g_csr_src[p] : 0;
    while (p < end) {
        int pn = p + 8;
        int srcn = (pn < end) ? g_csr_src[pn] : 0;   // prefetch next index
        float wv = expf(leaky(g_al2s[src] + ald));
        wsum += wv;
        uint2 hv = *(const uint2*)(g_h2h + (size_t)src * 16 + l * 4);
        float2 f0 = __half22float2(*(__half2*)&hv.x);
        float2 f1 = __half22float2(*(__half2*)&hv.y);
        acc[0] += wv * f0.x; acc[1] += wv * f0.y;
        acc[2] += wv * f1.x; acc[3] += wv * f1.y;
        p = pn;
        src = srcn;
    }

#pragma unroll
    for (int off = 4; off <= 16; off <<= 1) {
        wsum += __shfl_xor_sync(0xffffffffu, wsum, off);
#pragma unroll
        for (int j = 0; j < 4; j++)
            acc[j] += __shfl_xor_sync(0xffffffffu, acc[j], off);
    }

    // every lane holds the reduced sums for its l; finish log_softmax in-warp
    float inv = 1.f / wsum;
    float4 bb = __ldg((const float4*)b2 + l);
    float o0 = acc[0] * inv + bb.x;
    float o1 = acc[1] * inv + bb.y;
    float o2 = acc[2] * inv + bb.z;
    float o3 = acc[3] * inv + bb.w;
    float m = fmaxf(fmaxf(o0, o1), fmaxf(o2, o3));
#pragma unroll
    for (int off = 1; off <= 2; off <<= 1)
        m = fmaxf(m, __shfl_xor_sync(0xffffffffu, m, off, 4));
    float s = expf(o0 - m) + expf(o1 - m) + expf(o2 - m) + expf(o3 - m);
#pragma unroll
    for (int off = 1; off <= 2; off <<= 1)
        s += __shfl_xor_sync(0xffffffffu, s, off, 4);
    float lg = m + logf(s);

    if (sub == 0)
        *(float4*)(out + (size_t)i * 16 + l * 4) =
            make_float4(o0 - lg, o1 - lg, o2 - lg, o3 - lg);
}

// ---------------- launch: CSR build || gemm1 on two streams ----------------
extern "C" void kernel_launch(void* const* d_in, const int* in_sizes, int n_in,
                              void* d_out, int out_size) {
    const float* x   = (const float*)d_in[0];
    const void*  ei  = d_in[1];
    const float* W1  = (const float*)d_in[2];
    const float* a1s = (const float*)d_in[3];
    const float* a1d = (const float*)d_in[4];
    const float* b1  = (const float*)d_in[5];
    const float* W2  = (const float*)d_in[6];
    const float* a2s = (const float*)d_in[7];
    const float* a2d = (const float*)d_in[8];
    const float* b2  = (const float*)d_in[9];
    float* out = (float*)d_out;

    // fork: gemm1 on side stream, CSR build on main stream
    cudaEventRecord(g_ev_fork, 0);
    cudaStreamWaitEvent(g_s2, g_ev_fork, 0);
    gemm1_kernel<<<(N_NODES + 127) / 128, 256, 0, g_s2>>>(x, W1, a1s, a1d);
    cudaEventRecord(g_ev_join, g_s2);

    detect_zero_kernel<<<(N_NODES + 255) / 256, 256>>>((const int*)ei);
    hist_kernel<<<1563, 256>>>(ei);
    scan1_kernel<<<SCAN_NB, 1024>>>();                 // cross-block scan fused
    scan3_kernel<<<(N_NODES / 4 + 255) / 256, 256>>>();
    scatter_kernel<<<1563, 256>>>(ei);

    // join: edge1 needs both scatter (main) and gemm1 (side)
    cudaStreamWaitEvent(0, g_ev_join, 0);
    edge1_fused_kernel<<<(N_NODES * 32 + 255) / 256, 256>>>(W2, b1, a2s, a2d);
    edge2_csr_kernel<<<(N_NODES * 32 + 255) / 256, 256>>>(b2, out);   // final2 fused
}

// round 15
// speedup vs baseline: 1.0209x; 1.0209x over previous
#include <cuda_runtime.h>
#include <cuda_fp16.h>

#define N_NODES 100000
#define E_EDGES 1600000
#define FIN 512
#define HC1 64
#define H1 8
#define C2 16
#define NEG_SLOPE 0.2f
#define SCAN_NB ((N_NODES + 1023) / 1024)

// ---------------- scratch (static __device__, allocation-free) ----------------
__device__ __half g_h1h [(size_t)N_NODES * HC1];   // fp16 h1
__device__ float  g_al1s[(size_t)N_NODES * H1];
__device__ float  g_al1d[(size_t)N_NODES * H1];
__device__ float  g_acc1[(size_t)N_NODES * HC1];   // NORMALIZED layer-1 aggregate
__device__ __half g_h2h [(size_t)N_NODES * C2];    // fp16 h2 for edge2 gather
__device__ float  g_al2s[(size_t)N_NODES];
__device__ float  g_al2d[(size_t)N_NODES];
__device__ int    g_is64;
__device__ int    g_scan_ctr;

// CSR build scratch
__device__ int g_cnt      [N_NODES];
__device__ int g_incl     [N_NODES];
__device__ int g_part     [SCAN_NB + 1];
__device__ int g_row_start[N_NODES];
__device__ int g_row_end  [N_NODES];
__device__ int g_cursor   [N_NODES];
__device__ int g_csr_src  [E_EDGES];

// side stream + fork/join events (created once at program load; no device mem)
static cudaStream_t g_s2;
static cudaEvent_t  g_ev_fork, g_ev_join;
static bool g_stream_init = []() {
    cudaStreamCreateWithFlags(&g_s2, cudaStreamNonBlocking);
    cudaEventCreateWithFlags(&g_ev_fork, cudaEventDisableTiming);
    cudaEventCreateWithFlags(&g_ev_join, cudaEventDisableTiming);
    return true;
}();

__device__ __forceinline__ float leaky(float e) { return e > 0.f ? e : NEG_SLOPE * e; }

__device__ __forceinline__ float to_tf32(float f) {
    unsigned u;
    asm("cvt.rna.tf32.f32 %0, %1;" : "=r"(u) : "f"(f));
    return __uint_as_float(u);
}

// m16n8k8 tf32 mma, row.col, f32 accumulate
__device__ __forceinline__ void mma_tf32(float* d, const float* a, const float* b) {
    asm volatile(
        "mma.sync.aligned.m16n8k8.row.col.f32.tf32.tf32.f32 "
        "{%0,%1,%2,%3}, {%4,%5,%6,%7}, {%8,%9}, {%0,%1,%2,%3};\n"
        : "+f"(d[0]), "+f"(d[1]), "+f"(d[2]), "+f"(d[3])
        : "r"(__float_as_uint(a[0])), "r"(__float_as_uint(a[1])),
          "r"(__float_as_uint(a[2])), "r"(__float_as_uint(a[3])),
          "r"(__float_as_uint(b[0])), "r"(__float_as_uint(b[1])));
}

// ---------------- detect (int64 vs int32) + zero counters + reset scan ctr ----------------
__global__ void detect_zero_kernel(const int* __restrict__ ei_words) {
    int i = blockIdx.x * blockDim.x + threadIdx.x;
    if (i < N_NODES) g_cnt[i] = 0;
    if (blockIdx.x == 0) {
        __shared__ int nz;
        if (threadIdx.x == 0) nz = 0;
        __syncthreads();
        for (int j = threadIdx.x; j < 4096; j += blockDim.x)
            if (ei_words[2 * j + 1] != 0) nz = 1;
        __syncthreads();
        if (threadIdx.x == 0) {
            g_is64 = (nz == 0);
            g_scan_ctr = 0;
        }
    }
}

// ---------------- CSR build (vectorized, grid-strided) ----------------
__global__ void hist_kernel(const void* __restrict__ ei) {
    int t = blockIdx.x * blockDim.x + threadIdx.x;
    int stride = gridDim.x * blockDim.x;
    if (g_is64) {
        const longlong2* d = (const longlong2*)((const long long*)ei + E_EDGES);
        for (int j = t; j < E_EDGES / 2; j += stride) {
            longlong2 v = d[j];
            atomicAdd(&g_cnt[(int)v.x], 1);
            atomicAdd(&g_cnt[(int)v.y], 1);
        }
    } else {
        const int4* d = (const int4*)((const int*)ei + E_EDGES);
        for (int j = t; j < E_EDGES / 4; j += stride) {
            int4 v = d[j];
            atomicAdd(&g_cnt[v.x], 1);
            atomicAdd(&g_cnt[v.y], 1);
            atomicAdd(&g_cnt[v.z], 1);
            atomicAdd(&g_cnt[v.w], 1);
        }
    }
}

// block-level inclusive scan + fused cross-block exclusive scan in the last block
__global__ __launch_bounds__(1024) void scan1_kernel() {
    __shared__ int sm[1024];
    __shared__ int is_last;
    int i = blockIdx.x * 1024 + threadIdx.x;
    sm[threadIdx.x] = (i < N_NODES) ? g_cnt[i] : 0;
    __syncthreads();
#pragma unroll
    for (int off = 1; off < 1024; off <<= 1) {
        int t = (threadIdx.x >= off) ? sm[threadIdx.x - off] : 0;
        __syncthreads();
        sm[threadIdx.x] += t;
        __syncthreads();
    }
    if (i < N_NODES) g_incl[i] = sm[threadIdx.x];
    if (threadIdx.x == 1023) g_part[blockIdx.x] = sm[1023];
    __threadfence();
    if (threadIdx.x == 0)
        is_last = (atomicAdd(&g_scan_ctr, 1) == (int)gridDim.x - 1);
    __syncthreads();
    if (is_last && threadIdx.x < 32) {
        int lane = threadIdx.x;
        int run = 0;
        for (int b0 = 0; b0 < SCAN_NB; b0 += 32) {
            int idx = b0 + lane;
            int orig = (idx < SCAN_NB) ? g_part[idx] : 0;
            int v = orig;
#pragma unroll
            for (int off = 1; off < 32; off <<= 1) {
                int t = __shfl_up_sync(0xffffffffu, v, off);
                if (lane >= off) v += t;
            }
            if (idx < SCAN_NB) g_part[idx] = run + v - orig;  // exclusive
            run += __shfl_sync(0xffffffffu, v, 31);
        }
    }
}

// vectorized: 4 nodes per thread
__global__ void scan3_kernel() {
    int i4 = blockIdx.x * blockDim.x + threadIdx.x;
    if (i4 >= N_NODES / 4) return;
    int4 inc = ((const int4*)g_incl)[i4];
    int4 c   = ((const int4*)g_cnt)[i4];
    int part = g_part[(i4 * 4) >> 10];
    inc.x += part; inc.y += part; inc.z += part; inc.w += part;
    int4 st = make_int4(inc.x - c.x, inc.y - c.y, inc.z - c.z, inc.w - c.w);
    ((int4*)g_row_start)[i4] = st;
    ((int4*)g_row_end)[i4]   = inc;
    ((int4*)g_cursor)[i4]    = st;
}

__global__ void scatter_kernel(const void* __restrict__ ei) {
    int t = blockIdx.x * blockDim.x + threadIdx.x;
    int stride = gridDim.x * blockDim.x;
    if (g_is64) {
        const longlong2* s = (const longlong2*)((const long long*)ei);
        const longlong2* d = (const longlong2*)((const long long*)ei + E_EDGES);
        for (int j = t; j < E_EDGES / 2; j += stride) {
            longlong2 sv = s[j], dv = d[j];
            int p0 = atomicAdd(&g_cursor[(int)dv.x], 1);
            int p1 = atomicAdd(&g_cursor[(int)dv.y], 1);
            g_csr_src[p0] = (int)sv.x;
            g_csr_src[p1] = (int)sv.y;
        }
    } else {
        const int4* s = (const int4*)((const int*)ei);
        const int4* d = (const int4*)((const int*)ei + E_EDGES);
        for (int j = t; j < E_EDGES / 4; j += stride) {
            int4 sv = s[j], dv = d[j];
            int p0 = atomicAdd(&g_cursor[dv.x], 1);
            int p1 = atomicAdd(&g_cursor[dv.y], 1);
            int p2 = atomicAdd(&g_cursor[dv.z], 1);
            int p3 = atomicAdd(&g_cursor[dv.w], 1);
            g_csr_src[p0] = sv.x;
            g_csr_src[p1] = sv.y;
            g_csr_src[p2] = sv.z;
            g_csr_src[p3] = sv.w;
        }
    }
}

// ---------------- GEMM1 (tf32 mma, register double-buffered — proven R9): h1 = x @ W1 ----------------
__global__ __launch_bounds__(256) void gemm1_kernel(const float* __restrict__ x,
                                                    const float* __restrict__ W1,
                                                    const float* __restrict__ a1s,
                                                    const float* __restrict__ a1d) {
    __shared__ float As[128][36];
    __shared__ float Bs[32][72];
    const int tid = threadIdx.x;
    const int warp = tid >> 5, lane = tid & 31;
    const int gid = lane >> 2, tig = lane & 3;
    const int mw = (warp >> 1) * 32;
    const int nw = (warp & 1) * 32;
    const int block_row = blockIdx.x * 128;

    float acc[2][4][4];
#pragma unroll
    for (int mt = 0; mt < 2; mt++)
#pragma unroll
        for (int nt = 0; nt < 4; nt++)
#pragma unroll
            for (int j = 0; j < 4; j++) acc[mt][nt][j] = 0.f;

    float4 aR[4], bR[2];
    const int ar_r[4]  = { (tid) >> 3, (tid + 256) >> 3, (tid + 512) >> 3, (tid + 768) >> 3 };
    const int ar_c4 = tid & 7;
    const int b_kk[2]  = { tid >> 4, (tid + 256) >> 4 };
    const int b_n4 = tid & 15;

    auto gload = [&](int k0) {
#pragma unroll
        for (int p = 0; p < 4; p++) {
            int gr = block_row + ar_r[p];
            if (gr >= N_NODES) gr = N_NODES - 1;   // clamp; rows discarded in epilogue
            aR[p] = *(const float4*)(x + (size_t)gr * FIN + k0 + ar_c4 * 4);
        }
#pragma unroll
        for (int p = 0; p < 2; p++)
            bR[p] = *(const float4*)(W1 + (size_t)(k0 + b_kk[p]) * 64 + b_n4 * 4);
    };
    auto sstore = [&]() {
#pragma unroll
        for (int p = 0; p < 4; p++) {
            float4 v = aR[p];
            v.x = to_tf32(v.x); v.y = to_tf32(v.y);
            v.z = to_tf32(v.z); v.w = to_tf32(v.w);
            *(float4*)&As[ar_r[p]][ar_c4 * 4] = v;
        }
#pragma unroll
        for (int p = 0; p < 2; p++) {
            float4 v = bR[p];
            v.x = to_tf32(v.x); v.y = to_tf32(v.y);
            v.z = to_tf32(v.z); v.w = to_tf32(v.w);
            *(float4*)&Bs[b_kk[p]][b_n4 * 4] = v;
        }
    };

    gload(0);
    sstore();
    __syncthreads();

    for (int k0 = 0; k0 < FIN; k0 += 32) {
        bool more = (k0 + 32 < FIN);
        if (more) gload(k0 + 32);      // overlaps with compute below
#pragma unroll
        for (int kk = 0; kk < 32; kk += 8) {
            float a[2][4];
#pragma unroll
            for (int mt = 0; mt < 2; mt++) {
                int r = mw + mt * 16;
                a[mt][0] = As[r + gid][kk + tig];
                a[mt][1] = As[r + gid + 8][kk + tig];
                a[mt][2] = As[r + gid][kk + tig + 4];
                a[mt][3] = As[r + gid + 8][kk + tig + 4];
            }
            float b[4][2];
#pragma unroll
            for (int nt = 0; nt < 4; nt++) {
                b[nt][0] = Bs[kk + tig][nw + nt * 8 + gid];
                b[nt][1] = Bs[kk + tig + 4][nw + nt * 8 + gid];
            }
#pragma unroll
            for (int mt = 0; mt < 2; mt++)
#pragma unroll
                for (int nt = 0; nt < 4; nt++)
                    mma_tf32(acc[mt][nt], a[mt], b[nt]);
        }
        __syncthreads();
        if (more) {
            sstore();
            __syncthreads();
        }
    }

    // ---- epilogue: fp16 h1 + fused per-head attention logits ----
#pragma unroll
    for (int mt = 0; mt < 2; mt++) {
#pragma unroll
        for (int nt = 0; nt < 4; nt++) {
            int r0 = block_row + mw + mt * 16 + gid;
            int c = nw + nt * 8 + 2 * tig;
            int l = (nw + nt * 8) >> 3;          // head for this nt tile
            float as0 = __ldg(a1s + l * 8 + 2 * tig);
            float as1 = __ldg(a1s + l * 8 + 2 * tig + 1);
            float ad0 = __ldg(a1d + l * 8 + 2 * tig);
            float ad1 = __ldg(a1d + l * 8 + 2 * tig + 1);

            float vs  = acc[mt][nt][0] * as0 + acc[mt][nt][1] * as1;   // row r0
            float vd  = acc[mt][nt][0] * ad0 + acc[mt][nt][1] * ad1;
            float vs2 = acc[mt][nt][2] * as0 + acc[mt][nt][3] * as1;   // row r0+8
            float vd2 = acc[mt][nt][2] * ad0 + acc[mt][nt][3] * ad1;
#pragma unroll
            for (int off = 1; off <= 2; off <<= 1) {
                vs  += __shfl_xor_sync(0xffffffffu, vs,  off);
                vd  += __shfl_xor_sync(0xffffffffu, vd,  off);
                vs2 += __shfl_xor_sync(0xffffffffu, vs2, off);
                vd2 += __shfl_xor_sync(0xffffffffu, vd2, off);
            }

            if (r0 < N_NODES) {
                *(__half2*)(g_h1h + (size_t)r0 * 64 + c) =
                    __floats2half2_rn(acc[mt][nt][0], acc[mt][nt][1]);
                if (tig == 0) {
                    g_al1s[r0 * 8 + l] = vs;
                    g_al1d[r0 * 8 + l] = vd;
                }
            }
            if (r0 + 8 < N_NODES) {
                *(__half2*)(g_h1h + (size_t)(r0 + 8) * 64 + c) =
                    __floats2half2_rn(acc[mt][nt][2], acc[mt][nt][3]);
                if (tig == 0) {
                    g_al1s[(r0 + 8) * 8 + l] = vs2;
                    g_al1d[(r0 + 8) * 8 + l] = vd2;
                }
            }
        }
    }
}

// ---------------- edge1 (CSR pull, 3-stage pipeline): one warp per dst node ----------------
// Iteration k: issue idx(k+2), issue data(k+1), compute on data(k).
__global__ __launch_bounds__(256) void edge1_csr_kernel() {
    int w = (blockIdx.x * blockDim.x + threadIdx.x) >> 5;
    if (w >= N_NODES) return;
    const int lane = threadIdx.x & 31;
    const int sub = lane >> 3, l = lane & 7;
    const int i = w;

    float ald = g_al1d[i * 8 + l];
    float acc[8];
#pragma unroll
    for (int j = 0; j < 8; j++) acc[j] = 0.f;
    float wsum = 0.f;

    if (sub == 0) {  // self-loop
        float e = g_al1s[i * 8 + l] + ald;
        float ws = expf(leaky(e));
        wsum = ws;
        uint4 hv = *(const uint4*)(g_h1h + (size_t)i * 64 + l * 8);
        float2 f0 = __half22float2(*(__half2*)&hv.x);
        float2 f1 = __half22float2(*(__half2*)&hv.y);
        float2 f2 = __half22float2(*(__half2*)&hv.z);
        float2 f3 = __half22float2(*(__half2*)&hv.w);
        acc[0] = ws * f0.x; acc[1] = ws * f0.y;
        acc[2] = ws * f1.x; acc[3] = ws * f1.y;
        acc[4] = ws * f2.x; acc[5] = ws * f2.y;
        acc[6] = ws * f3.x; acc[7] = ws * f3.y;
    }

    const int end = g_row_end[i];
    int p = g_row_start[i] + sub;
    int p1 = p + 4;
    // prologue: idx(0), idx(1), data(0)
    int src1 = (p1 < end) ? g_csr_src[p1] : 0;
    uint4 hv0 = make_uint4(0, 0, 0, 0);
    float es0 = 0.f;
    if (p < end) {
        int src0 = g_csr_src[p];
        hv0 = *(const uint4*)(g_h1h + (size_t)src0 * 64 + l * 8);
        es0 = g_al1s[src0 * 8 + l];
    }
    while (p < end) {
        int p2 = p1 + 4;
        int src2 = (p2 < end) ? g_csr_src[p2] : 0;       // idx(k+2)
        uint4 hv1 = make_uint4(0, 0, 0, 0);
        float es1 = 0.f;
        if (p1 < end) {                                   // data(k+1)
            hv1 = *(const uint4*)(g_h1h + (size_t)src1 * 64 + l * 8);
            es1 = g_al1s[src1 * 8 + l];
        }
        // compute(k)
        float wv = expf(leaky(es0 + ald));
        wsum += wv;
        float2 f0 = __half22float2(*(__half2*)&hv0.x);
        float2 f1 = __half22float2(*(__half2*)&hv0.y);
        float2 f2 = __half22float2(*(__half2*)&hv0.z);
        float2 f3 = __half22float2(*(__half2*)&hv0.w);
        acc[0] += wv * f0.x; acc[1] += wv * f0.y;
        acc[2] += wv * f1.x; acc[3] += wv * f1.y;
        acc[4] += wv * f2.x; acc[5] += wv * f2.y;
        acc[6] += wv * f3.x; acc[7] += wv * f3.y;
        p = p1; p1 = p2; src1 = src2; hv0 = hv1; es0 = es1;
    }

#pragma unroll
    for (int off = 8; off <= 16; off <<= 1) {
        wsum += __shfl_xor_sync(0xffffffffu, wsum, off);
#pragma unroll
        for (int j = 0; j < 8; j++)
            acc[j] += __shfl_xor_sync(0xffffffffu, acc[j], off);
    }

    if (sub == 0) {
        float inv = 1.f / wsum;
        *(float4*)(g_acc1 + (size_t)i * 64 + l * 8) =
            make_float4(acc[0] * inv, acc[1] * inv, acc[2] * inv, acc[3] * inv);
        *(float4*)(g_acc1 + (size_t)i * 64 + l * 8 + 4) =
            make_float4(acc[4] * inv, acc[5] * inv, acc[6] * inv, acc[7] * inv);
    }
}

// ---------------- final1: bias + ELU + GEMM2 + layer-2 attn logits ----------------
__global__ __launch_bounds__(256) void final1_kernel(const float* __restrict__ W2,
                                                     const float* __restrict__ b1,
                                                     const float* __restrict__ a2s,
                                                     const float* __restrict__ a2d) {
    __shared__ float W2s[64 * 16];
    __shared__ float vbuf[16][64];
    const int tid = threadIdx.x;
    for (int j = tid; j < 64 * 16; j += 256) W2s[j] = W2[j];
    __syncthreads();

    int nl = tid >> 4, c = tid & 15;
    int i = blockIdx.x * 16 + nl;

    if (i < N_NODES) {
        float4 a = *(const float4*)(g_acc1 + (size_t)i * 64 + c * 4);
        float4 bb = *(const float4*)(b1 + c * 4);
        float v0 = a.x + bb.x;
        float v1 = a.y + bb.y;
        float v2 = a.z + bb.z;
        float v3 = a.w + bb.w;
        v0 = v0 > 0.f ? v0 : expf(v0) - 1.f;
        v1 = v1 > 0.f ? v1 : expf(v1) - 1.f;
        v2 = v2 > 0.f ? v2 : expf(v2) - 1.f;
        v3 = v3 > 0.f ? v3 : expf(v3) - 1.f;
        vbuf[nl][c * 4 + 0] = v0;
        vbuf[nl][c * 4 + 1] = v1;
        vbuf[nl][c * 4 + 2] = v2;
        vbuf[nl][c * 4 + 3] = v3;
    }
    __syncwarp();

    float h2c = 0.f;
    if (i < N_NODES) {
#pragma unroll
        for (int j = 0; j < 64; j++) h2c += vbuf[nl][j] * W2s[j * 16 + c];
    }
    float als = h2c * a2s[c];
    float ald = h2c * a2d[c];
#pragma unroll
    for (int off = 8; off > 0; off >>= 1) {
        als += __shfl_down_sync(0xffffffffu, als, off, 16);
        ald += __shfl_down_sync(0xffffffffu, ald, off, 16);
    }
    als = __shfl_sync(0xffffffffu, als, 0, 16);
    ald = __shfl_sync(0xffffffffu, ald, 0, 16);

    if (i < N_NODES) {
        g_h2h[i * 16 + c] = __float2half_rn(h2c);
        if (c == 0) {
            g_al2s[i] = als;
            g_al2d[i] = ald;
        }
    }
}

// ---------------- edge2 (CSR pull, 3-stage pipeline) + fused bias/log_softmax ----------------
__global__ __launch_bounds__(256) void edge2_csr_kernel(const float* __restrict__ b2,
                                                        float* __restrict__ out) {
    int w = (blockIdx.x * blockDim.x + threadIdx.x) >> 5;
    if (w >= N_NODES) return;
    const int lane = threadIdx.x & 31;
    const int sub = lane >> 2, l = lane & 3;
    const int i = w;

    float ald = g_al2d[i];
    float acc[4];
#pragma unroll
    for (int j = 0; j < 4; j++) acc[j] = 0.f;
    float wsum = 0.f;

    if (sub == 0) {  // self-loop
        float ws = expf(leaky(g_al2s[i] + ald));
        wsum = ws;
        uint2 hv = *(const uint2*)(g_h2h + (size_t)i * 16 + l * 4);
        float2 f0 = __half22float2(*(__half2*)&hv.x);
        float2 f1 = __half22float2(*(__half2*)&hv.y);
        acc[0] = ws * f0.x; acc[1] = ws * f0.y;
        acc[2] = ws * f1.x; acc[3] = ws * f1.y;
    }

    const int end = g_row_end[i];
    int p = g_row_start[i] + sub;
    int p1 = p + 8;
    int src1 = (p1 < end) ? g_csr_src[p1] : 0;
    uint2 hv0 = make_uint2(0, 0);
    float es0 = 0.f;
    if (p < end) {
        int src0 = g_csr_src[p];
        hv0 = *(const uint2*)(g_h2h + (size_t)src0 * 16 + l * 4);
        es0 = g_al2s[src0];
    }
    while (p < end) {
        int p2 = p1 + 8;
        int src2 = (p2 < end) ? g_csr_src[p2] : 0;       // idx(k+2)
        uint2 hv1 = make_uint2(0, 0);
        float es1 = 0.f;
        if (p1 < end) {                                   // data(k+1)
            hv1 = *(const uint2*)(g_h2h + (size_t)src1 * 16 + l * 4);
            es1 = g_al2s[src1];
        }
        // compute(k)
        float wv = expf(leaky(es0 + ald));
        wsum += wv;
        float2 f0 = __half22float2(*(__half2*)&hv0.x);
        float2 f1 = __half22float2(*(__half2*)&hv0.y);
        acc[0] += wv * f0.x; acc[1] += wv * f0.y;
        acc[2] += wv * f1.x; acc[3] += wv * f1.y;
        p = p1; p1 = p2; src1 = src2; hv0 = hv1; es0 = es1;
    }

#pragma unroll
    for (int off = 4; off <= 16; off <<= 1) {
        wsum += __shfl_xor_sync(0xffffffffu, wsum, off);
#pragma unroll
        for (int j = 0; j < 4; j++)
            acc[j] += __shfl_xor_sync(0xffffffffu, acc[j], off);
    }

    // every lane holds the reduced sums for its l; finish log_softmax in-warp
    float inv = 1.f / wsum;
    float4 bb = __ldg((const float4*)b2 + l);
    float o0 = acc[0] * inv + bb.x;
    float o1 = acc[1] * inv + bb.y;
    float o2 = acc[2] * inv + bb.z;
    float o3 = acc[3] * inv + bb.w;
    float m = fmaxf(fmaxf(o0, o1), fmaxf(o2, o3));
#pragma unroll
    for (int off = 1; off <= 2; off <<= 1)
        m = fmaxf(m, __shfl_xor_sync(0xffffffffu, m, off, 4));
    float s = expf(o0 - m) + expf(o1 - m) + expf(o2 - m) + expf(o3 - m);
#pragma unroll
    for (int off = 1; off <= 2; off <<= 1)
        s += __shfl_xor_sync(0xffffffffu, s, off, 4);
    float lg = m + logf(s);

    if (sub == 0)
        *(float4*)(out + (size_t)i * 16 + l * 4) =
            make_float4(o0 - lg, o1 - lg, o2 - lg, o3 - lg);
}

// ---------------- launch: CSR build || gemm1 on two streams ----------------
extern "C" void kernel_launch(void* const* d_in, const int* in_sizes, int n_in,
                              void* d_out, int out_size) {
    const float* x   = (const float*)d_in[0];
    const void*  ei  = d_in[1];
    const float* W1  = (const float*)d_in[2];
    const float* a1s = (const float*)d_in[3];
    const float* a1d = (const float*)d_in[4];
    const float* b1  = (const float*)d_in[5];
    const float* W2  = (const float*)d_in[6];
    const float* a2s = (const float*)d_in[7];
    const float* a2d = (const float*)d_in[8];
    const float* b2  = (const float*)d_in[9];
    float* out = (float*)d_out;

    // fork: gemm1 on side stream, CSR build on main stream
    cudaEventRecord(g_ev_fork, 0);
    cudaStreamWaitEvent(g_s2, g_ev_fork, 0);
    gemm1_kernel<<<(N_NODES + 127) / 128, 256, 0, g_s2>>>(x, W1, a1s, a1d);
    cudaEventRecord(g_ev_join, g_s2);

    detect_zero_kernel<<<(N_NODES + 255) / 256, 256>>>((const int*)ei);
    hist_kernel<<<1563, 256>>>(ei);
    scan1_kernel<<<SCAN_NB, 1024>>>();                 // cross-block scan fused
    scan3_kernel<<<(N_NODES / 4 + 255) / 256, 256>>>();
    scatter_kernel<<<1563, 256>>>(ei);

    // join: edge1 needs both scatter (main) and gemm1 (side)
    cudaStreamWaitEvent(0, g_ev_join, 0);
    edge1_csr_kernel<<<(N_NODES * 32 + 255) / 256, 256>>>();
    final1_kernel<<<(N_NODES + 15) / 16, 256>>>(W2, b1, a2s, a2d);
    edge2_csr_kernel<<<(N_NODES * 32 + 255) / 256, 256>>>(b2, out);
}

// round 16
// speedup vs baseline: 1.0303x; 1.0091x over previous
#include <cuda_runtime.h>
#include <cuda_fp16.h>

#define N_NODES 100000
#define E_EDGES 1600000
#define FIN 512
#define HC1 64
#define H1 8
#define C2 16
#define NEG_SLOPE 0.2f
#define SCAN_NB ((N_NODES + 1023) / 1024)

// ---------------- scratch (static __device__, allocation-free) ----------------
__device__ __half g_h1h [(size_t)N_NODES * HC1];   // fp16 h1
__device__ float  g_al1s[(size_t)N_NODES * H1];
__device__ float  g_al1d[(size_t)N_NODES * H1];
__device__ float  g_acc1[(size_t)N_NODES * HC1];   // NORMALIZED layer-1 aggregate
__device__ __half g_h2h [(size_t)N_NODES * C2];    // fp16 h2 for edge2 gather
__device__ float  g_al2s[(size_t)N_NODES];
__device__ float  g_al2d[(size_t)N_NODES];
__device__ int    g_is64;
__device__ int    g_scan_ctr;

// CSR build scratch
__device__ int g_cnt      [N_NODES];
__device__ int g_incl     [N_NODES];
__device__ int g_part     [SCAN_NB + 1];
__device__ int g_row_start[N_NODES];
__device__ int g_row_end  [N_NODES];
__device__ int g_cursor   [N_NODES];
__device__ int g_csr_src  [E_EDGES];

// side stream + fork/join events (created once at program load; no device mem)
static cudaStream_t g_s2;
static cudaEvent_t  g_ev_fork, g_ev_join;
static bool g_stream_init = []() {
    cudaStreamCreateWithFlags(&g_s2, cudaStreamNonBlocking);
    cudaEventCreateWithFlags(&g_ev_fork, cudaEventDisableTiming);
    cudaEventCreateWithFlags(&g_ev_join, cudaEventDisableTiming);
    return true;
}();

__device__ __forceinline__ float leaky(float e) { return e > 0.f ? e : NEG_SLOPE * e; }

// m16n8k16 fp16 mma, row.col, f32 accumulate
__device__ __forceinline__ void mma_f16(float* d, const unsigned* a, const unsigned* b) {
    asm volatile(
        "mma.sync.aligned.m16n8k16.row.col.f32.f16.f16.f32 "
        "{%0,%1,%2,%3}, {%4,%5,%6,%7}, {%8,%9}, {%0,%1,%2,%3};\n"
        : "+f"(d[0]), "+f"(d[1]), "+f"(d[2]), "+f"(d[3])
        : "r"(a[0]), "r"(a[1]), "r"(a[2]), "r"(a[3]),
          "r"(b[0]), "r"(b[1]));
}

// ---------------- detect (int64 vs int32) + zero counters + reset scan ctr ----------------
__global__ void detect_zero_kernel(const int* __restrict__ ei_words) {
    int i = blockIdx.x * blockDim.x + threadIdx.x;
    if (i < N_NODES) g_cnt[i] = 0;
    if (blockIdx.x == 0) {
        __shared__ int nz;
        if (threadIdx.x == 0) nz = 0;
        __syncthreads();
        for (int j = threadIdx.x; j < 4096; j += blockDim.x)
            if (ei_words[2 * j + 1] != 0) nz = 1;
        __syncthreads();
        if (threadIdx.x == 0) {
            g_is64 = (nz == 0);
            g_scan_ctr = 0;
        }
    }
}

// ---------------- CSR build (vectorized, grid-strided) ----------------
__global__ void hist_kernel(const void* __restrict__ ei) {
    int t = blockIdx.x * blockDim.x + threadIdx.x;
    int stride = gridDim.x * blockDim.x;
    if (g_is64) {
        const longlong2* d = (const longlong2*)((const long long*)ei + E_EDGES);
        for (int j = t; j < E_EDGES / 2; j += stride) {
            longlong2 v = d[j];
            atomicAdd(&g_cnt[(int)v.x], 1);
            atomicAdd(&g_cnt[(int)v.y], 1);
        }
    } else {
        const int4* d = (const int4*)((const int*)ei + E_EDGES);
        for (int j = t; j < E_EDGES / 4; j += stride) {
            int4 v = d[j];
            atomicAdd(&g_cnt[v.x], 1);
            atomicAdd(&g_cnt[v.y], 1);
            atomicAdd(&g_cnt[v.z], 1);
            atomicAdd(&g_cnt[v.w], 1);
        }
    }
}

// block-level inclusive scan + fused cross-block exclusive scan in the last block
__global__ __launch_bounds__(1024) void scan1_kernel() {
    __shared__ int sm[1024];
    __shared__ int is_last;
    int i = blockIdx.x * 1024 + threadIdx.x;
    sm[threadIdx.x] = (i < N_NODES) ? g_cnt[i] : 0;
    __syncthreads();
#pragma unroll
    for (int off = 1; off < 1024; off <<= 1) {
        int t = (threadIdx.x >= off) ? sm[threadIdx.x - off] : 0;
        __syncthreads();
        sm[threadIdx.x] += t;
        __syncthreads();
    }
    if (i < N_NODES) g_incl[i] = sm[threadIdx.x];
    if (threadIdx.x == 1023) g_part[blockIdx.x] = sm[1023];
    __threadfence();
    if (threadIdx.x == 0)
        is_last = (atomicAdd(&g_scan_ctr, 1) == (int)gridDim.x - 1);
    __syncthreads();
    if (is_last && threadIdx.x < 32) {
        int lane = threadIdx.x;
        int run = 0;
        for (int b0 = 0; b0 < SCAN_NB; b0 += 32) {
            int idx = b0 + lane;
            int orig = (idx < SCAN_NB) ? g_part[idx] : 0;
            int v = orig;
#pragma unroll
            for (int off = 1; off < 32; off <<= 1) {
                int t = __shfl_up_sync(0xffffffffu, v, off);
                if (lane >= off) v += t;
            }
            if (idx < SCAN_NB) g_part[idx] = run + v - orig;  // exclusive
            run += __shfl_sync(0xffffffffu, v, 31);
        }
    }
}

// vectorized: 4 nodes per thread
__global__ void scan3_kernel() {
    int i4 = blockIdx.x * blockDim.x + threadIdx.x;
    if (i4 >= N_NODES / 4) return;
    int4 inc = ((const int4*)g_incl)[i4];
    int4 c   = ((const int4*)g_cnt)[i4];
    int part = g_part[(i4 * 4) >> 10];
    inc.x += part; inc.y += part; inc.z += part; inc.w += part;
    int4 st = make_int4(inc.x - c.x, inc.y - c.y, inc.z - c.z, inc.w - c.w);
    ((int4*)g_row_start)[i4] = st;
    ((int4*)g_row_end)[i4]   = inc;
    ((int4*)g_cursor)[i4]    = st;
}

__global__ void scatter_kernel(const void* __restrict__ ei) {
    int t = blockIdx.x * blockDim.x + threadIdx.x;
    int stride = gridDim.x * blockDim.x;
    if (g_is64) {
        const longlong2* s = (const longlong2*)((const long long*)ei);
        const longlong2* d = (const longlong2*)((const long long*)ei + E_EDGES);
        for (int j = t; j < E_EDGES / 2; j += stride) {
            longlong2 sv = s[j], dv = d[j];
            int p0 = atomicAdd(&g_cursor[(int)dv.x], 1);
            int p1 = atomicAdd(&g_cursor[(int)dv.y], 1);
            g_csr_src[p0] = (int)sv.x;
            g_csr_src[p1] = (int)sv.y;
        }
    } else {
        const int4* s = (const int4*)((const int*)ei);
        const int4* d = (const int4*)((const int*)ei + E_EDGES);
        for (int j = t; j < E_EDGES / 4; j += stride) {
            int4 sv = s[j], dv = d[j];
            int p0 = atomicAdd(&g_cursor[dv.x], 1);
            int p1 = atomicAdd(&g_cursor[dv.y], 1);
            int p2 = atomicAdd(&g_cursor[dv.z], 1);
            int p3 = atomicAdd(&g_cursor[dv.w], 1);
            g_csr_src[p0] = sv.x;
            g_csr_src[p1] = sv.y;
            g_csr_src[p2] = sv.z;
            g_csr_src[p3] = sv.w;
        }
    }
}

// ---------------- GEMM1 (fp16 m16n8k16 mma, register double-buffered): h1 = x @ W1 ----------------
// CTA tile 128x64, BK=32, 8 warps (4x2), warp 32x32; fused attn logits epilogue.
// A in smem [128][40] halves (pad 40 -> conflict-free frag loads);
// B TRANSPOSED in smem [64][40] halves so b-frags are contiguous half2 along k.
__global__ __launch_bounds__(256) void gemm1_kernel(const float* __restrict__ x,
                                                    const float* __restrict__ W1,
                                                    const float* __restrict__ a1s,
                                                    const float* __restrict__ a1d) {
    __shared__ __half As[128][40];
    __shared__ __half Bst[64][40];
    const int tid = threadIdx.x;
    const int warp = tid >> 5, lane = tid & 31;
    const int gid = lane >> 2, tig = lane & 3;
    const int mw = (warp >> 1) * 32;
    const int nw = (warp & 1) * 32;
    const int block_row = blockIdx.x * 128;

    float acc[2][4][4];
#pragma unroll
    for (int mt = 0; mt < 2; mt++)
#pragma unroll
        for (int nt = 0; nt < 4; nt++)
#pragma unroll
            for (int j = 0; j < 4; j++) acc[mt][nt][j] = 0.f;

    float4 aR[4], bR[2];
    const int ar_r[4]  = { (tid) >> 3, (tid + 256) >> 3, (tid + 512) >> 3, (tid + 768) >> 3 };
    const int ar_c4 = tid & 7;
    const int b_kk[2]  = { tid >> 4, (tid + 256) >> 4 };
    const int b_n4 = tid & 15;

    auto gload = [&](int k0) {
#pragma unroll
        for (int p = 0; p < 4; p++) {
            int gr = block_row + ar_r[p];
            if (gr >= N_NODES) gr = N_NODES - 1;   // clamp; rows discarded in epilogue
            aR[p] = *(const float4*)(x + (size_t)gr * FIN + k0 + ar_c4 * 4);
        }
#pragma unroll
        for (int p = 0; p < 2; p++)
            bR[p] = *(const float4*)(W1 + (size_t)(k0 + b_kk[p]) * 64 + b_n4 * 4);
    };
    auto sstore = [&]() {
#pragma unroll
        for (int p = 0; p < 4; p++) {
            float4 v = aR[p];
            *(__half2*)&As[ar_r[p]][ar_c4 * 4]     = __floats2half2_rn(v.x, v.y);
            *(__half2*)&As[ar_r[p]][ar_c4 * 4 + 2] = __floats2half2_rn(v.z, v.w);
        }
#pragma unroll
        for (int p = 0; p < 2; p++) {
            float4 v = bR[p];
            int n0 = b_n4 * 4, kk = b_kk[p];
            Bst[n0 + 0][kk] = __float2half_rn(v.x);
            Bst[n0 + 1][kk] = __float2half_rn(v.y);
            Bst[n0 + 2][kk] = __float2half_rn(v.z);
            Bst[n0 + 3][kk] = __float2half_rn(v.w);
        }
    };

    gload(0);
    sstore();
    __syncthreads();

    for (int k0 = 0; k0 < FIN; k0 += 32) {
        bool more = (k0 + 32 < FIN);
        if (more) gload(k0 + 32);      // overlaps with compute below
#pragma unroll
        for (int kk = 0; kk < 32; kk += 16) {
            unsigned a[2][4];
#pragma unroll
            for (int mt = 0; mt < 2; mt++) {
                int r = mw + mt * 16;
                a[mt][0] = *(const unsigned*)&As[r + gid][kk + 2 * tig];
                a[mt][1] = *(const unsigned*)&As[r + gid + 8][kk + 2 * tig];
                a[mt][2] = *(const unsigned*)&As[r + gid][kk + 2 * tig + 8];
                a[mt][3] = *(const unsigned*)&As[r + gid + 8][kk + 2 * tig + 8];
            }
            unsigned b[4][2];
#pragma unroll
            for (int nt = 0; nt < 4; nt++) {
                int n = nw + nt * 8 + gid;
                b[nt][0] = *(const unsigned*)&Bst[n][kk + 2 * tig];
                b[nt][1] = *(const unsigned*)&Bst[n][kk + 2 * tig + 8];
            }
#pragma unroll
            for (int mt = 0; mt < 2; mt++)
#pragma unroll
                for (int nt = 0; nt < 4; nt++)
                    mma_f16(acc[mt][nt], a[mt], b[nt]);
        }
        __syncthreads();
        if (more) {
            sstore();
            __syncthreads();
        }
    }

    // ---- epilogue: fp16 h1 + fused per-head attention logits (layout identical) ----
#pragma unroll
    for (int mt = 0; mt < 2; mt++) {
#pragma unroll
        for (int nt = 0; nt < 4; nt++) {
            int r0 = block_row + mw + mt * 16 + gid;
            int c = nw + nt * 8 + 2 * tig;
            int l = (nw + nt * 8) >> 3;          // head for this nt tile
            float as0 = __ldg(a1s + l * 8 + 2 * tig);
            float as1 = __ldg(a1s + l * 8 + 2 * tig + 1);
            float ad0 = __ldg(a1d + l * 8 + 2 * tig);
            float ad1 = __ldg(a1d + l * 8 + 2 * tig + 1);

            float vs  = acc[mt][nt][0] * as0 + acc[mt][nt][1] * as1;   // row r0
            float vd  = acc[mt][nt][0] * ad0 + acc[mt][nt][1] * ad1;
            float vs2 = acc[mt][nt][2] * as0 + acc[mt][nt][3] * as1;   // row r0+8
            float vd2 = acc[mt][nt][2] * ad0 + acc[mt][nt][3] * ad1;
#pragma unroll
            for (int off = 1; off <= 2; off <<= 1) {
                vs  += __shfl_xor_sync(0xffffffffu, vs,  off);
                vd  += __shfl_xor_sync(0xffffffffu, vd,  off);
                vs2 += __shfl_xor_sync(0xffffffffu, vs2, off);
                vd2 += __shfl_xor_sync(0xffffffffu, vd2, off);
            }

            if (r0 < N_NODES) {
                *(__half2*)(g_h1h + (size_t)r0 * 64 + c) =
                    __floats2half2_rn(acc[mt][nt][0], acc[mt][nt][1]);
                if (tig == 0) {
                    g_al1s[r0 * 8 + l] = vs;
                    g_al1d[r0 * 8 + l] = vd;
                }
            }
            if (r0 + 8 < N_NODES) {
                *(__half2*)(g_h1h + (size_t)(r0 + 8) * 64 + c) =
                    __floats2half2_rn(acc[mt][nt][2], acc[mt][nt][3]);
                if (tig == 0) {
                    g_al1s[(r0 + 8) * 8 + l] = vs2;
                    g_al1d[(r0 + 8) * 8 + l] = vd2;
                }
            }
        }
    }
}

// ---------------- edge1 (CSR pull, 3-stage pipeline): one warp per dst node ----------------
__global__ __launch_bounds__(256) void edge1_csr_kernel() {
    int w = (blockIdx.x * blockDim.x + threadIdx.x) >> 5;
    if (w >= N_NODES) return;
    const int lane = threadIdx.x & 31;
    const int sub = lane >> 3, l = lane & 7;
    const int i = w;

    float ald = g_al1d[i * 8 + l];
    float acc[8];
#pragma unroll
    for (int j = 0; j < 8; j++) acc[j] = 0.f;
    float wsum = 0.f;

    if (sub == 0) {  // self-loop
        float e = g_al1s[i * 8 + l] + ald;
        float ws = expf(leaky(e));
        wsum = ws;
        uint4 hv = *(const uint4*)(g_h1h + (size_t)i * 64 + l * 8);
        float2 f0 = __half22float2(*(__half2*)&hv.x);
        float2 f1 = __half22float2(*(__half2*)&hv.y);
        float2 f2 = __half22float2(*(__half2*)&hv.z);
        float2 f3 = __half22float2(*(__half2*)&hv.w);
        acc[0] = ws * f0.x; acc[1] = ws * f0.y;
        acc[2] = ws * f1.x; acc[3] = ws * f1.y;
        acc[4] = ws * f2.x; acc[5] = ws * f2.y;
        acc[6] = ws * f3.x; acc[7] = ws * f3.y;
    }

    const int end = g_row_end[i];
    int p = g_row_start[i] + sub;
    int p1 = p + 4;
    int src1 = (p1 < end) ? g_csr_src[p1] : 0;
    uint4 hv0 = make_uint4(0, 0, 0, 0);
    float es0 = 0.f;
    if (p < end) {
        int src0 = g_csr_src[p];
        hv0 = *(const uint4*)(g_h1h + (size_t)src0 * 64 + l * 8);
        es0 = g_al1s[src0 * 8 + l];
    }
    while (p < end) {
        int p2 = p1 + 4;
        int src2 = (p2 < end) ? g_csr_src[p2] : 0;       // idx(k+2)
        uint4 hv1 = make_uint4(0, 0, 0, 0);
        float es1 = 0.f;
        if (p1 < end) {                                   // data(k+1)
            hv1 = *(const uint4*)(g_h1h + (size_t)src1 * 64 + l * 8);
            es1 = g_al1s[src1 * 8 + l];
        }
        // compute(k)
        float wv = expf(leaky(es0 + ald));
        wsum += wv;
        float2 f0 = __half22float2(*(__half2*)&hv0.x);
        float2 f1 = __half22float2(*(__half2*)&hv0.y);
        float2 f2 = __half22float2(*(__half2*)&hv0.z);
        float2 f3 = __half22float2(*(__half2*)&hv0.w);
        acc[0] += wv * f0.x; acc[1] += wv * f0.y;
        acc[2] += wv * f1.x; acc[3] += wv * f1.y;
        acc[4] += wv * f2.x; acc[5] += wv * f2.y;
        acc[6] += wv * f3.x; acc[7] += wv * f3.y;
        p = p1; p1 = p2; src1 = src2; hv0 = hv1; es0 = es1;
    }

#pragma unroll
    for (int off = 8; off <= 16; off <<= 1) {
        wsum += __shfl_xor_sync(0xffffffffu, wsum, off);
#pragma unroll
        for (int j = 0; j < 8; j++)
            acc[j] += __shfl_xor_sync(0xffffffffu, acc[j], off);
    }

    if (sub == 0) {
        float inv = 1.f / wsum;
        *(float4*)(g_acc1 + (size_t)i * 64 + l * 8) =
            make_float4(acc[0] * inv, acc[1] * inv, acc[2] * inv, acc[3] * inv);
        *(float4*)(g_acc1 + (size_t)i * 64 + l * 8 + 4) =
            make_float4(acc[4] * inv, acc[5] * inv, acc[6] * inv, acc[7] * inv);
    }
}

// ---------------- final1: bias + ELU + GEMM2 + layer-2 attn logits ----------------
__global__ __launch_bounds__(256) void final1_kernel(const float* __restrict__ W2,
                                                     const float* __restrict__ b1,
                                                     const float* __restrict__ a2s,
                                                     const float* __restrict__ a2d) {
    __shared__ float W2s[64 * 16];
    __shared__ float vbuf[16][64];
    const int tid = threadIdx.x;
    for (int j = tid; j < 64 * 16; j += 256) W2s[j] = W2[j];
    __syncthreads();

    int nl = tid >> 4, c = tid & 15;
    int i = blockIdx.x * 16 + nl;

    if (i < N_NODES) {
        float4 a = *(const float4*)(g_acc1 + (size_t)i * 64 + c * 4);
        float4 bb = *(const float4*)(b1 + c * 4);
        float v0 = a.x + bb.x;
        float v1 = a.y + bb.y;
        float v2 = a.z + bb.z;
        float v3 = a.w + bb.w;
        v0 = v0 > 0.f ? v0 : expf(v0) - 1.f;
        v1 = v1 > 0.f ? v1 : expf(v1) - 1.f;
        v2 = v2 > 0.f ? v2 : expf(v2) - 1.f;
        v3 = v3 > 0.f ? v3 : expf(v3) - 1.f;
        vbuf[nl][c * 4 + 0] = v0;
        vbuf[nl][c * 4 + 1] = v1;
        vbuf[nl][c * 4 + 2] = v2;
        vbuf[nl][c * 4 + 3] = v3;
    }
    __syncwarp();

    float h2c = 0.f;
    if (i < N_NODES) {
#pragma unroll
        for (int j = 0; j < 64; j++) h2c += vbuf[nl][j] * W2s[j * 16 + c];
    }
    float als = h2c * a2s[c];
    float ald = h2c * a2d[c];
#pragma unroll
    for (int off = 8; off > 0; off >>= 1) {
        als += __shfl_down_sync(0xffffffffu, als, off, 16);
        ald += __shfl_down_sync(0xffffffffu, ald, off, 16);
    }
    als = __shfl_sync(0xffffffffu, als, 0, 16);
    ald = __shfl_sync(0xffffffffu, ald, 0, 16);

    if (i < N_NODES) {
        g_h2h[i * 16 + c] = __float2half_rn(h2c);
        if (c == 0) {
            g_al2s[i] = als;
            g_al2d[i] = ald;
        }
    }
}

// ---------------- edge2 (CSR pull, 3-stage pipeline) + fused bias/log_softmax ----------------
__global__ __launch_bounds__(256) void edge2_csr_kernel(const float* __restrict__ b2,
                                                        float* __restrict__ out) {
    int w = (blockIdx.x * blockDim.x + threadIdx.x) >> 5;
    if (w >= N_NODES) return;
    const int lane = threadIdx.x & 31;
    const int sub = lane >> 2, l = lane & 3;
    const int i = w;

    float ald = g_al2d[i];
    float acc[4];
#pragma unroll
    for (int j = 0; j < 4; j++) acc[j] = 0.f;
    float wsum = 0.f;

    if (sub == 0) {  // self-loop
        float ws = expf(leaky(g_al2s[i] + ald));
        wsum = ws;
        uint2 hv = *(const uint2*)(g_h2h + (size_t)i * 16 + l * 4);
        float2 f0 = __half22float2(*(__half2*)&hv.x);
        float2 f1 = __half22float2(*(__half2*)&hv.y);
        acc[0] = ws * f0.x; acc[1] = ws * f0.y;
        acc[2] = ws * f1.x; acc[3] = ws * f1.y;
    }

    const int end = g_row_end[i];
    int p = g_row_start[i] + sub;
    int p1 = p + 8;
    int src1 = (p1 < end) ? g_csr_src[p1] : 0;
    uint2 hv0 = make_uint2(0, 0);
    float es0 = 0.f;
    if (p < end) {
        int src0 = g_csr_src[p];
        hv0 = *(const uint2*)(g_h2h + (size_t)src0 * 16 + l * 4);
        es0 = g_al2s[src0];
    }
    while (p < end) {
        int p2 = p1 + 8;
        int src2 = (p2 < end) ? g_csr_src[p2] : 0;       // idx(k+2)
        uint2 hv1 = make_uint2(0, 0);
        float es1 = 0.f;
        if (p1 < end) {                                   // data(k+1)
            hv1 = *(const uint2*)(g_h2h + (size_t)src1 * 16 + l * 4);
            es1 = g_al2s[src1];
        }
        // compute(k)
        float wv = expf(leaky(es0 + ald));
        wsum += wv;
        float2 f0 = __half22float2(*(__half2*)&hv0.x);
        float2 f1 = __half22float2(*(__half2*)&hv0.y);
        acc[0] += wv * f0.x; acc[1] += wv * f0.y;
        acc[2] += wv * f1.x; acc[3] += wv * f1.y;
        p = p1; p1 = p2; src1 = src2; hv0 = hv1; es0 = es1;
    }

#pragma unroll
    for (int off = 4; off <= 16; off <<= 1) {
        wsum += __shfl_xor_sync(0xffffffffu, wsum, off);
#pragma unroll
        for (int j = 0; j < 4; j++)
            acc[j] += __shfl_xor_sync(0xffffffffu, acc[j], off);
    }

    // every lane holds the reduced sums for its l; finish log_softmax in-warp
    float inv = 1.f / wsum;
    float4 bb = __ldg((const float4*)b2 + l);
    float o0 = acc[0] * inv + bb.x;
    float o1 = acc[1] * inv + bb.y;
    float o2 = acc[2] * inv + bb.z;
    float o3 = acc[3] * inv + bb.w;
    float m = fmaxf(fmaxf(o0, o1), fmaxf(o2, o3));
#pragma unroll
    for (int off = 1; off <= 2; off <<= 1)
        m = fmaxf(m, __shfl_xor_sync(0xffffffffu, m, off, 4));
    float s = expf(o0 - m) + expf(o1 - m) + expf(o2 - m) + expf(o3 - m);
#pragma unroll
    for (int off = 1; off <= 2; off <<= 1)
        s += __shfl_xor_sync(0xffffffffu, s, off, 4);
    float lg = m + logf(s);

    if (sub == 0)
        *(float4*)(out + (size_t)i * 16 + l * 4) =
            make_float4(o0 - lg, o1 - lg, o2 - lg, o3 - lg);
}

// ---------------- launch: CSR build || gemm1 on two streams ----------------
extern "C" void kernel_launch(void* const* d_in, const int* in_sizes, int n_in,
                              void* d_out, int out_size) {
    const float* x   = (const float*)d_in[0];
    const void*  ei  = d_in[1];
    const float* W1  = (const float*)d_in[2];
    const float* a1s = (const float*)d_in[3];
    const float* a1d = (const float*)d_in[4];
    const float* b1  = (const float*)d_in[5];
    const float* W2  = (const float*)d_in[6];
    const float* a2s = (const float*)d_in[7];
    const float* a2d = (const float*)d_in[8];
    const float* b2  = (const float*)d_in[9];
    float* out = (float*)d_out;

    // fork: gemm1 on side stream, CSR build on main stream
    cudaEventRecord(g_ev_fork, 0);
    cudaStreamWaitEvent(g_s2, g_ev_fork, 0);
    gemm1_kernel<<<(N_NODES + 127) / 128, 256, 0, g_s2>>>(x, W1, a1s, a1d);
    cudaEventRecord(g_ev_join, g_s2);

    detect_zero_kernel<<<(N_NODES + 255) / 256, 256>>>((const int*)ei);
    hist_kernel<<<1563, 256>>>(ei);
    scan1_kernel<<<SCAN_NB, 1024>>>();                 // cross-block scan fused
    scan3_kernel<<<(N_NODES / 4 + 255) / 256, 256>>>();
    scatter_kernel<<<1563, 256>>>(ei);

    // join: edge1 needs both scatter (main) and gemm1 (side)
    cudaStreamWaitEvent(0, g_ev_join, 0);
    edge1_csr_kernel<<<(N_NODES * 32 + 255) / 256, 256>>>();
    final1_kernel<<<(N_NODES + 15) / 16, 256>>>(W2, b1, a2s, a2d);
    edge2_csr_kernel<<<(N_NODES * 32 + 255) / 256, 256>>>(b2, out);
}

// round 17
// speedup vs baseline: 1.0694x; 1.0380x over previous
#include <cuda_runtime.h>
#include <cuda_fp16.h>

#define N_NODES 100000
#define E_EDGES 1600000
#define FIN 512
#define HC1 64
#define H1 8
#define C2 16
#define NEG_SLOPE 0.2f
#define SCAN_NB4 ((N_NODES + 4095) / 4096)   // 25 blocks, 4 nodes/thread

// ---------------- scratch (static __device__, allocation-free) ----------------
__device__ __half g_h1h  [(size_t)N_NODES * HC1];  // fp16 h1
__device__ float  g_al1s [(size_t)N_NODES * H1];
__device__ float  g_al1d [(size_t)N_NODES * H1];
__device__ __half g_acc1h[(size_t)N_NODES * HC1];  // NORMALIZED layer-1 aggregate (fp16)
__device__ __half g_h2h  [(size_t)N_NODES * C2];   // fp16 h2 for edge2 gather
__device__ float  g_al2s [(size_t)N_NODES];
__device__ float  g_al2d [(size_t)N_NODES];
__device__ int    g_is64;
__device__ int    g_scan_ctr;

// CSR build scratch
__device__ int g_cnt      [N_NODES];
__device__ int g_incl     [N_NODES];
__device__ int g_part     [SCAN_NB4 + 1];
__device__ int g_row_start[N_NODES];
__device__ int g_row_end  [N_NODES];
__device__ int g_cursor   [N_NODES];
__device__ int g_csr_src  [E_EDGES];

// side stream + fork/join events (created once at program load; no device mem)
static cudaStream_t g_s2;
static cudaEvent_t  g_ev_fork, g_ev_join;
static bool g_stream_init = []() {
    cudaStreamCreateWithFlags(&g_s2, cudaStreamNonBlocking);
    cudaEventCreateWithFlags(&g_ev_fork, cudaEventDisableTiming);
    cudaEventCreateWithFlags(&g_ev_join, cudaEventDisableTiming);
    return true;
}();

__device__ __forceinline__ float leaky(float e) { return e > 0.f ? e : NEG_SLOPE * e; }

// m16n8k16 fp16 mma, row.col, f32 accumulate
__device__ __forceinline__ void mma_f16(float* d, const unsigned* a, const unsigned* b) {
    asm volatile(
        "mma.sync.aligned.m16n8k16.row.col.f32.f16.f16.f32 "
        "{%0,%1,%2,%3}, {%4,%5,%6,%7}, {%8,%9}, {%0,%1,%2,%3};\n"
        : "+f"(d[0]), "+f"(d[1]), "+f"(d[2]), "+f"(d[3])
        : "r"(a[0]), "r"(a[1]), "r"(a[2]), "r"(a[3]),
          "r"(b[0]), "r"(b[1]));
}

// ---------------- detect (int64 vs int32) + zero counters + reset scan ctr ----------------
__global__ void detect_zero_kernel(const int* __restrict__ ei_words) {
    int i = blockIdx.x * blockDim.x + threadIdx.x;
    if (i < N_NODES) g_cnt[i] = 0;
    if (blockIdx.x == 0) {
        __shared__ int nz;
        if (threadIdx.x == 0) nz = 0;
        __syncthreads();
        for (int j = threadIdx.x; j < 4096; j += blockDim.x)
            if (ei_words[2 * j + 1] != 0) nz = 1;
        __syncthreads();
        if (threadIdx.x == 0) {
            g_is64 = (nz == 0);
            g_scan_ctr = 0;
        }
    }
}

// ---------------- CSR build (vectorized, grid-strided) ----------------
__global__ void hist_kernel(const void* __restrict__ ei) {
    int t = blockIdx.x * blockDim.x + threadIdx.x;
    int stride = gridDim.x * blockDim.x;
    if (g_is64) {
        const longlong2* d = (const longlong2*)((const long long*)ei + E_EDGES);
        for (int j = t; j < E_EDGES / 2; j += stride) {
            longlong2 v = d[j];
            atomicAdd(&g_cnt[(int)v.x], 1);
            atomicAdd(&g_cnt[(int)v.y], 1);
        }
    } else {
        const int4* d = (const int4*)((const int*)ei + E_EDGES);
        for (int j = t; j < E_EDGES / 4; j += stride) {
            int4 v = d[j];
            atomicAdd(&g_cnt[v.x], 1);
            atomicAdd(&g_cnt[v.y], 1);
            atomicAdd(&g_cnt[v.z], 1);
            atomicAdd(&g_cnt[v.w], 1);
        }
    }
}

// block scan: 4 nodes/thread (int4), 25 blocks; fused cross-block scan in last block
__global__ __launch_bounds__(1024) void scan1_kernel() {
    __shared__ int sm[1024];
    __shared__ int is_last;
    int base = blockIdx.x * 4096 + threadIdx.x * 4;
    int4 v4 = make_int4(0, 0, 0, 0);
    if (base + 3 < N_NODES) {
        v4 = *(const int4*)(g_cnt + base);
    } else {
        if (base + 0 < N_NODES) v4.x = g_cnt[base + 0];
        if (base + 1 < N_NODES) v4.y = g_cnt[base + 1];
        if (base + 2 < N_NODES) v4.z = g_cnt[base + 2];
        if (base + 3 < N_NODES) v4.w = g_cnt[base + 3];
    }
    int s0 = v4.x, s1 = s0 + v4.y, s2 = s1 + v4.z, s3 = s2 + v4.w;
    sm[threadIdx.x] = s3;
    __syncthreads();
#pragma unroll
    for (int off = 1; off < 1024; off <<= 1) {
        int t = (threadIdx.x >= off) ? sm[threadIdx.x - off] : 0;
        __syncthreads();
        sm[threadIdx.x] += t;
        __syncthreads();
    }
    int excl = sm[threadIdx.x] - s3;    // exclusive offset of this thread's group
    if (base + 3 < N_NODES) {
        *(int4*)(g_incl + base) = make_int4(excl + s0, excl + s1, excl + s2, excl + s3);
    } else {
        if (base + 0 < N_NODES) g_incl[base + 0] = excl + s0;
        if (base + 1 < N_NODES) g_incl[base + 1] = excl + s1;
        if (base + 2 < N_NODES) g_incl[base + 2] = excl + s2;
        if (base + 3 < N_NODES) g_incl[base + 3] = excl + s3;
    }
    if (threadIdx.x == 1023) g_part[blockIdx.x] = sm[1023];
    __threadfence();
    if (threadIdx.x == 0)
        is_last = (atomicAdd(&g_scan_ctr, 1) == (int)gridDim.x - 1);
    __syncthreads();
    if (is_last && threadIdx.x < 32) {
        int lane = threadIdx.x;
        int orig = (lane < SCAN_NB4) ? g_part[lane] : 0;   // SCAN_NB4 <= 32
        int v = orig;
#pragma unroll
        for (int off = 1; off < 32; off <<= 1) {
            int t = __shfl_up_sync(0xffffffffu, v, off);
            if (lane >= off) v += t;
        }
        if (lane < SCAN_NB4) g_part[lane] = v - orig;      // exclusive
    }
}

// vectorized: 4 nodes per thread (part index: node>>12 == i4>>10)
__global__ void scan3_kernel() {
    int i4 = blockIdx.x * blockDim.x + threadIdx.x;
    if (i4 >= N_NODES / 4) return;
    int4 inc = ((const int4*)g_incl)[i4];
    int4 c   = ((const int4*)g_cnt)[i4];
    int part = g_part[i4 >> 10];
    inc.x += part; inc.y += part; inc.z += part; inc.w += part;
    int4 st = make_int4(inc.x - c.x, inc.y - c.y, inc.z - c.z, inc.w - c.w);
    ((int4*)g_row_start)[i4] = st;
    ((int4*)g_row_end)[i4]   = inc;
    ((int4*)g_cursor)[i4]    = st;
}

__global__ void scatter_kernel(const void* __restrict__ ei) {
    int t = blockIdx.x * blockDim.x + threadIdx.x;
    int stride = gridDim.x * blockDim.x;
    if (g_is64) {
        const longlong2* s = (const longlong2*)((const long long*)ei);
        const longlong2* d = (const longlong2*)((const long long*)ei + E_EDGES);
        for (int j = t; j < E_EDGES / 2; j += stride) {
            longlong2 sv = s[j], dv = d[j];
            int p0 = atomicAdd(&g_cursor[(int)dv.x], 1);
            int p1 = atomicAdd(&g_cursor[(int)dv.y], 1);
            g_csr_src[p0] = (int)sv.x;
            g_csr_src[p1] = (int)sv.y;
        }
    } else {
        const int4* s = (const int4*)((const int*)ei);
        const int4* d = (const int4*)((const int*)ei + E_EDGES);
        for (int j = t; j < E_EDGES / 4; j += stride) {
            int4 sv = s[j], dv = d[j];
            int p0 = atomicAdd(&g_cursor[dv.x], 1);
            int p1 = atomicAdd(&g_cursor[dv.y], 1);
            int p2 = atomicAdd(&g_cursor[dv.z], 1);
            int p3 = atomicAdd(&g_cursor[dv.w], 1);
            g_csr_src[p0] = sv.x;
            g_csr_src[p1] = sv.y;
            g_csr_src[p2] = sv.z;
            g_csr_src[p3] = sv.w;
        }
    }
}

// ---------------- GEMM1 (fp16 m16n8k16 mma, register double-buffered): h1 = x @ W1 ----------------
__global__ __launch_bounds__(256) void gemm1_kernel(const float* __restrict__ x,
                                                    const float* __restrict__ W1,
                                                    const float* __restrict__ a1s,
                                                    const float* __restrict__ a1d) {
    __shared__ __half As[128][40];
    __shared__ __half Bst[64][40];
    const int tid = threadIdx.x;
    const int warp = tid >> 5, lane = tid & 31;
    const int gid = lane >> 2, tig = lane & 3;
    const int mw = (warp >> 1) * 32;
    const int nw = (warp & 1) * 32;
    const int block_row = blockIdx.x * 128;

    float acc[2][4][4];
#pragma unroll
    for (int mt = 0; mt < 2; mt++)
#pragma unroll
        for (int nt = 0; nt < 4; nt++)
#pragma unroll
            for (int j = 0; j < 4; j++) acc[mt][nt][j] = 0.f;

    float4 aR[4], bR[2];
    const int ar_r[4]  = { (tid) >> 3, (tid + 256) >> 3, (tid + 512) >> 3, (tid + 768) >> 3 };
    const int ar_c4 = tid & 7;
    const int b_kk[2]  = { tid >> 4, (tid + 256) >> 4 };
    const int b_n4 = tid & 15;

    auto gload = [&](int k0) {
#pragma unroll
        for (int p = 0; p < 4; p++) {
            int gr = block_row + ar_r[p];
            if (gr >= N_NODES) gr = N_NODES - 1;   // clamp; rows discarded in epilogue
            aR[p] = *(const float4*)(x + (size_t)gr * FIN + k0 + ar_c4 * 4);
        }
#pragma unroll
        for (int p = 0; p < 2; p++)
            bR[p] = *(const float4*)(W1 + (size_t)(k0 + b_kk[p]) * 64 + b_n4 * 4);
    };
    auto sstore = [&]() {
#pragma unroll
        for (int p = 0; p < 4; p++) {
            float4 v = aR[p];
            *(__half2*)&As[ar_r[p]][ar_c4 * 4]     = __floats2half2_rn(v.x, v.y);
            *(__half2*)&As[ar_r[p]][ar_c4 * 4 + 2] = __floats2half2_rn(v.z, v.w);
        }
#pragma unroll
        for (int p = 0; p < 2; p++) {
            float4 v = bR[p];
            int n0 = b_n4 * 4, kk = b_kk[p];
            Bst[n0 + 0][kk] = __float2half_rn(v.x);
            Bst[n0 + 1][kk] = __float2half_rn(v.y);
            Bst[n0 + 2][kk] = __float2half_rn(v.z);
            Bst[n0 + 3][kk] = __float2half_rn(v.w);
        }
    };

    gload(0);
    sstore();
    __syncthreads();

    for (int k0 = 0; k0 < FIN; k0 += 32) {
        bool more = (k0 + 32 < FIN);
        if (more) gload(k0 + 32);      // overlaps with compute below
#pragma unroll
        for (int kk = 0; kk < 32; kk += 16) {
            unsigned a[2][4];
#pragma unroll
            for (int mt = 0; mt < 2; mt++) {
                int r = mw + mt * 16;
                a[mt][0] = *(const unsigned*)&As[r + gid][kk + 2 * tig];
                a[mt][1] = *(const unsigned*)&As[r + gid + 8][kk + 2 * tig];
                a[mt][2] = *(const unsigned*)&As[r + gid][kk + 2 * tig + 8];
                a[mt][3] = *(const unsigned*)&As[r + gid + 8][kk + 2 * tig + 8];
            }
            unsigned b[4][2];
#pragma unroll
            for (int nt = 0; nt < 4; nt++) {
                int n = nw + nt * 8 + gid;
                b[nt][0] = *(const unsigned*)&Bst[n][kk + 2 * tig];
                b[nt][1] = *(const unsigned*)&Bst[n][kk + 2 * tig + 8];
            }
#pragma unroll
            for (int mt = 0; mt < 2; mt++)
#pragma unroll
                for (int nt = 0; nt < 4; nt++)
                    mma_f16(acc[mt][nt], a[mt], b[nt]);
        }
        __syncthreads();
        if (more) {
            sstore();
            __syncthreads();
        }
    }

    // ---- epilogue: fp16 h1 + fused per-head attention logits ----
#pragma unroll
    for (int mt = 0; mt < 2; mt++) {
#pragma unroll
        for (int nt = 0; nt < 4; nt++) {
            int r0 = block_row + mw + mt * 16 + gid;
            int c = nw + nt * 8 + 2 * tig;
            int l = (nw + nt * 8) >> 3;          // head for this nt tile
            float as0 = __ldg(a1s + l * 8 + 2 * tig);
            float as1 = __ldg(a1s + l * 8 + 2 * tig + 1);
            float ad0 = __ldg(a1d + l * 8 + 2 * tig);
            float ad1 = __ldg(a1d + l * 8 + 2 * tig + 1);

            float vs  = acc[mt][nt][0] * as0 + acc[mt][nt][1] * as1;   // row r0
            float vd  = acc[mt][nt][0] * ad0 + acc[mt][nt][1] * ad1;
            float vs2 = acc[mt][nt][2] * as0 + acc[mt][nt][3] * as1;   // row r0+8
            float vd2 = acc[mt][nt][2] * ad0 + acc[mt][nt][3] * ad1;
#pragma unroll
            for (int off = 1; off <= 2; off <<= 1) {
                vs  += __shfl_xor_sync(0xffffffffu, vs,  off);
                vd  += __shfl_xor_sync(0xffffffffu, vd,  off);
                vs2 += __shfl_xor_sync(0xffffffffu, vs2, off);
                vd2 += __shfl_xor_sync(0xffffffffu, vd2, off);
            }

            if (r0 < N_NODES) {
                *(__half2*)(g_h1h + (size_t)r0 * 64 + c) =
                    __floats2half2_rn(acc[mt][nt][0], acc[mt][nt][1]);
                if (tig == 0) {
                    g_al1s[r0 * 8 + l] = vs;
                    g_al1d[r0 * 8 + l] = vd;
                }
            }
            if (r0 + 8 < N_NODES) {
                *(__half2*)(g_h1h + (size_t)(r0 + 8) * 64 + c) =
                    __floats2half2_rn(acc[mt][nt][2], acc[mt][nt][3]);
                if (tig == 0) {
                    g_al1s[(r0 + 8) * 8 + l] = vs2;
                    g_al1d[(r0 + 8) * 8 + l] = vd2;
                }
            }
        }
    }
}

// ---------------- edge1 (CSR pull, 3-stage pipeline): one warp per dst node ----------------
// fp16 normalized aggregate out (one STG.128 per lane-group).
__global__ __launch_bounds__(256) void edge1_csr_kernel() {
    int w = (blockIdx.x * blockDim.x + threadIdx.x) >> 5;
    if (w >= N_NODES) return;
    const int lane = threadIdx.x & 31;
    const int sub = lane >> 3, l = lane & 7;
    const int i = w;

    float ald = g_al1d[i * 8 + l];
    float acc[8];
#pragma unroll
    for (int j = 0; j < 8; j++) acc[j] = 0.f;
    float wsum = 0.f;

    if (sub == 0) {  // self-loop
        float e = g_al1s[i * 8 + l] + ald;
        float ws = expf(leaky(e));
        wsum = ws;
        uint4 hv = *(const uint4*)(g_h1h + (size_t)i * 64 + l * 8);
        float2 f0 = __half22float2(*(__half2*)&hv.x);
        float2 f1 = __half22float2(*(__half2*)&hv.y);
        float2 f2 = __half22float2(*(__half2*)&hv.z);
        float2 f3 = __half22float2(*(__half2*)&hv.w);
        acc[0] = ws * f0.x; acc[1] = ws * f0.y;
        acc[2] = ws * f1.x; acc[3] = ws * f1.y;
        acc[4] = ws * f2.x; acc[5] = ws * f2.y;
        acc[6] = ws * f3.x; acc[7] = ws * f3.y;
    }

    const int end = g_row_end[i];
    int p = g_row_start[i] + sub;
    int p1 = p + 4;
    int src1 = (p1 < end) ? g_csr_src[p1] : 0;
    uint4 hv0 = make_uint4(0, 0, 0, 0);
    float es0 = 0.f;
    if (p < end) {
        int src0 = g_csr_src[p];
        hv0 = *(const uint4*)(g_h1h + (size_t)src0 * 64 + l * 8);
        es0 = g_al1s[src0 * 8 + l];
    }
    while (p < end) {
        int p2 = p1 + 4;
        int src2 = (p2 < end) ? g_csr_src[p2] : 0;       // idx(k+2)
        uint4 hv1 = make_uint4(0, 0, 0, 0);
        float es1 = 0.f;
        if (p1 < end) {                                   // data(k+1)
            hv1 = *(const uint4*)(g_h1h + (size_t)src1 * 64 + l * 8);
            es1 = g_al1s[src1 * 8 + l];
        }
        // compute(k)
        float wv = expf(leaky(es0 + ald));
        wsum += wv;
        float2 f0 = __half22float2(*(__half2*)&hv0.x);
        float2 f1 = __half22float2(*(__half2*)&hv0.y);
        float2 f2 = __half22float2(*(__half2*)&hv0.z);
        float2 f3 = __half22float2(*(__half2*)&hv0.w);
        acc[0] += wv * f0.x; acc[1] += wv * f0.y;
        acc[2] += wv * f1.x; acc[3] += wv * f1.y;
        acc[4] += wv * f2.x; acc[5] += wv * f2.y;
        acc[6] += wv * f3.x; acc[7] += wv * f3.y;
        p = p1; p1 = p2; src1 = src2; hv0 = hv1; es0 = es1;
    }

#pragma unroll
    for (int off = 8; off <= 16; off <<= 1) {
        wsum += __shfl_xor_sync(0xffffffffu, wsum, off);
#pragma unroll
        for (int j = 0; j < 8; j++)
            acc[j] += __shfl_xor_sync(0xffffffffu, acc[j], off);
    }

    if (sub == 0) {
        float inv = 1.f / wsum;
        __half2 q0 = __floats2half2_rn(acc[0] * inv, acc[1] * inv);
        __half2 q1 = __floats2half2_rn(acc[2] * inv, acc[3] * inv);
        __half2 q2 = __floats2half2_rn(acc[4] * inv, acc[5] * inv);
        __half2 q3 = __floats2half2_rn(acc[6] * inv, acc[7] * inv);
        uint4 pack;
        pack.x = *(unsigned*)&q0; pack.y = *(unsigned*)&q1;
        pack.z = *(unsigned*)&q2; pack.w = *(unsigned*)&q3;
        *(uint4*)(g_acc1h + (size_t)i * 64 + l * 8) = pack;
    }
}

// ---------------- final1: bias + ELU + GEMM2 + layer-2 attn logits ----------------
__global__ __launch_bounds__(256) void final1_kernel(const float* __restrict__ W2,
                                                     const float* __restrict__ b1,
                                                     const float* __restrict__ a2s,
                                                     const float* __restrict__ a2d) {
    __shared__ float W2s[64 * 16];
    __shared__ float vbuf[16][64];
    const int tid = threadIdx.x;
    for (int j = tid; j < 64 * 16; j += 256) W2s[j] = W2[j];
    __syncthreads();

    int nl = tid >> 4, c = tid & 15;
    int i = blockIdx.x * 16 + nl;

    if (i < N_NODES) {
        uint2 a = *(const uint2*)(g_acc1h + (size_t)i * 64 + c * 4);
        float2 p0 = __half22float2(*(__half2*)&a.x);
        float2 p1 = __half22float2(*(__half2*)&a.y);
        float4 bb = *(const float4*)(b1 + c * 4);
        float v0 = p0.x + bb.x;
        float v1 = p0.y + bb.y;
        float v2 = p1.x + bb.z;
        float v3 = p1.y + bb.w;
        v0 = v0 > 0.f ? v0 : expf(v0) - 1.f;
        v1 = v1 > 0.f ? v1 : expf(v1) - 1.f;
        v2 = v2 > 0.f ? v2 : expf(v2) - 1.f;
        v3 = v3 > 0.f ? v3 : expf(v3) - 1.f;
        vbuf[nl][c * 4 + 0] = v0;
        vbuf[nl][c * 4 + 1] = v1;
        vbuf[nl][c * 4 + 2] = v2;
        vbuf[nl][c * 4 + 3] = v3;
    }
    __syncwarp();

    float h2c = 0.f;
    if (i < N_NODES) {
#pragma unroll
        for (int j = 0; j < 64; j++) h2c += vbuf[nl][j] * W2s[j * 16 + c];
    }
    float als = h2c * a2s[c];
    float ald = h2c * a2d[c];
#pragma unroll
    for (int off = 8; off > 0; off >>= 1) {
        als += __shfl_down_sync(0xffffffffu, als, off, 16);
        ald += __shfl_down_sync(0xffffffffu, ald, off, 16);
    }
    als = __shfl_sync(0xffffffffu, als, 0, 16);
    ald = __shfl_sync(0xffffffffu, ald, 0, 16);

    if (i < N_NODES) {
        g_h2h[i * 16 + c] = __float2half_rn(h2c);
        if (c == 0) {
            g_al2s[i] = als;
            g_al2d[i] = ald;
        }
    }
}

// ---------------- edge2 (CSR pull, 3-stage pipeline) + fused bias/log_softmax ----------------
__global__ __launch_bounds__(256) void edge2_csr_kernel(const float* __restrict__ b2,
                                                        float* __restrict__ out) {
    int w = (blockIdx.x * blockDim.x + threadIdx.x) >> 5;
    if (w >= N_NODES) return;
    const int lane = threadIdx.x & 31;
    const int sub = lane >> 2, l = lane & 3;
    const int i = w;

    float ald = g_al2d[i];
    float acc[4];
#pragma unroll
    for (int j = 0; j < 4; j++) acc[j] = 0.f;
    float wsum = 0.f;

    if (sub == 0) {  // self-loop
        float ws = expf(leaky(g_al2s[i] + ald));
        wsum = ws;
        uint2 hv = *(const uint2*)(g_h2h + (size_t)i * 16 + l * 4);
        float2 f0 = __half22float2(*(__half2*)&hv.x);
        float2 f1 = __half22float2(*(__half2*)&hv.y);
        acc[0] = ws * f0.x; acc[1] = ws * f0.y;
        acc[2] = ws * f1.x; acc[3] = ws * f1.y;
    }

    const int end = g_row_end[i];
    int p = g_row_start[i] + sub;
    int p1 = p + 8;
    int src1 = (p1 < end) ? g_csr_src[p1] : 0;
    uint2 hv0 = make_uint2(0, 0);
    float es0 = 0.f;
    if (p < end) {
        int src0 = g_csr_src[p];
        hv0 = *(const uint2*)(g_h2h + (size_t)src0 * 16 + l * 4);
        es0 = g_al2s[src0];
    }
    while (p < end) {
        int p2 = p1 + 8;
        int src2 = (p2 < end) ? g_csr_src[p2] : 0;       // idx(k+2)
        uint2 hv1 = make_uint2(0, 0);
        float es1 = 0.f;
        if (p1 < end) {                                   // data(k+1)
            hv1 = *(const uint2*)(g_h2h + (size_t)src1 * 16 + l * 4);
            es1 = g_al2s[src1];
        }
        // compute(k)
        float wv = expf(leaky(es0 + ald));
        wsum += wv;
        float2 f0 = __half22float2(*(__half2*)&hv0.x);
        float2 f1 = __half22float2(*(__half2*)&hv0.y);
        acc[0] += wv * f0.x; acc[1] += wv * f0.y;
        acc[2] += wv * f1.x; acc[3] += wv * f1.y;
        p = p1; p1 = p2; src1 = src2; hv0 = hv1; es0 = es1;
    }

#pragma unroll
    for (int off = 4; off <= 16; off <<= 1) {
        wsum += __shfl_xor_sync(0xffffffffu, wsum, off);
#pragma unroll
        for (int j = 0; j < 4; j++)
            acc[j] += __shfl_xor_sync(0xffffffffu, acc[j], off);
    }

    // every lane holds the reduced sums for its l; finish log_softmax in-warp
    float inv = 1.f / wsum;
    float4 bb = __ldg((const float4*)b2 + l);
    float o0 = acc[0] * inv + bb.x;
    float o1 = acc[1] * inv + bb.y;
    float o2 = acc[2] * inv + bb.z;
    float o3 = acc[3] * inv + bb.w;
    float m = fmaxf(fmaxf(o0, o1), fmaxf(o2, o3));
#pragma unroll
    for (int off = 1; off <= 2; off <<= 1)
        m = fmaxf(m, __shfl_xor_sync(0xffffffffu, m, off, 4));
    float s = expf(o0 - m) + expf(o1 - m) + expf(o2 - m) + expf(o3 - m);
#pragma unroll
    for (int off = 1; off <= 2; off <<= 1)
        s += __shfl_xor_sync(0xffffffffu, s, off, 4);
    float lg = m + logf(s);

    if (sub == 0)
        *(float4*)(out + (size_t)i * 16 + l * 4) =
            make_float4(o0 - lg, o1 - lg, o2 - lg, o3 - lg);
}

// ---------------- launch: CSR build || gemm1 on two streams ----------------
extern "C" void kernel_launch(void* const* d_in, const int* in_sizes, int n_in,
                              void* d_out, int out_size) {
    const float* x   = (const float*)d_in[0];
    const void*  ei  = d_in[1];
    const float* W1  = (const float*)d_in[2];
    const float* a1s = (const float*)d_in[3];
    const float* a1d = (const float*)d_in[4];
    const float* b1  = (const float*)d_in[5];
    const float* W2  = (const float*)d_in[6];
    const float* a2s = (const float*)d_in[7];
    const float* a2d = (const float*)d_in[8];
    const float* b2  = (const float*)d_in[9];
    float* out = (float*)d_out;

    // fork: gemm1 on side stream, CSR build on main stream
    cudaEventRecord(g_ev_fork, 0);
    cudaStreamWaitEvent(g_s2, g_ev_fork, 0);
    gemm1_kernel<<<(N_NODES + 127) / 128, 256, 0, g_s2>>>(x, W1, a1s, a1d);
    cudaEventRecord(g_ev_join, g_s2);

    detect_zero_kernel<<<(N_NODES + 255) / 256, 256>>>((const int*)ei);
    hist_kernel<<<1563, 256>>>(ei);
    scan1_kernel<<<SCAN_NB4, 1024>>>();                // cross-block scan fused
    scan3_kernel<<<(N_NODES / 4 + 255) / 256, 256>>>();
    scatter_kernel<<<1563, 256>>>(ei);

    // join: edge1 needs both scatter (main) and gemm1 (side)
    cudaStreamWaitEvent(0, g_ev_join, 0);
    edge1_csr_kernel<<<(N_NODES * 32 + 255) / 256, 256>>>();
    final1_kernel<<<(N_NODES + 15) / 16, 256>>>(W2, b1, a2s, a2d);
    edge2_csr_kernel<<<(N_NODES * 32 + 255) / 256, 256>>>(b2, out);
}